// round 7
// baseline (speedup 1.0000x reference)
#include <cuda_runtime.h>
#include <math.h>

#define BB   4
#define CC   64
#define HH   192
#define WW   192
#define HWX  (HH*WW)
#define OFFC 18
#define HID  4

typedef unsigned long long u64;

// packed fp32x2 FMA: d = a*b + d (lane-wise, exact IEEE fp32)
#define FMA2(d, a, b) asm("fma.rn.f32x2 %0, %1, %2, %0;" : "+l"(d) : "l"(a), "l"(b))
#define UNPK(lo, hi, v) asm("mov.b64 {%0,%1}, %2;" : "=f"(lo), "=f"(hi) : "l"(v))

// scratch (device globals; allocations are forbidden)
__device__ float g_off[BB*OFFC*HH*WW];        // 10.6 MB
__device__ float g_h  [BB*CC*HH*WW];          // 37.7 MB
__device__ float g_pool[BB*CC];               // post-BN channel sums
__device__ float g_cw  [BB*CC];
__device__ float g_dwT  [9*CC*CC];            // [kk][o][c]
__device__ float g_offwT[CC*9*OFFC];          // [(c*9+t)*18 + o]

// dynamic smem layout for deform kernel (in floats)
#define DW_S_OFF    0                          // 4096 floats (one tap [o][c])
#define SAMP_PITCH  132                        // 2*64 px + pad (16B-aligned rows)
#define SAMP_S_OFF  (DW_S_OFF + CC*CC)         // 32 c2-rows * 132
#define DEFORM_SMEM_FLOATS (SAMP_S_OFF + 32*SAMP_PITCH)
#define DEFORM_SMEM_BYTES  (DEFORM_SMEM_FLOATS * 4)   // 33280 B

// ---------------------------------------------------------------------------
// K0: weight transposes + zero pool accumulators (once per launch; tiny)
// ---------------------------------------------------------------------------
__global__ __launch_bounds__(256) void transpose_w_kernel(
        const float* __restrict__ dw, const float* __restrict__ off_w) {
    int d = blockIdx.x*256 + threadIdx.x;
    if (blockIdx.x == 0) g_pool[threadIdx.x] = 0.f;
    if (d < 9*CC*CC) {
        int kk = d >> 12;
        int o  = (d >> 6) & 63;
        int c  = d & 63;
        g_dwT[d] = dw[(o*CC + c)*9 + kk];
    } else {
        int e = d - 9*CC*CC;
        if (e < CC*9*OFFC) {
            int k = e / OFFC;      // c*9+t
            int o = e % OFFC;
            int c = k / 9, t = k % 9;
            g_offwT[e] = off_w[(o*CC + c)*9 + t];
        }
    }
}

// ---------------------------------------------------------------------------
// K1: 3x3 conv 64 -> 18 (offset prediction), pad 1
// tile 64x8, 256 threads, 2 pixels/thread (x and x+32); grid (3, 24, 4)
// ---------------------------------------------------------------------------
__global__ __launch_bounds__(256) void offset_conv_kernel(
        const float* __restrict__ x,
        const float* __restrict__ off_b) {
    __shared__ float wsm[CC*9*OFFC];   // [(c*9+t)*18+o]  41.5 KB
    __shared__ float xs[10*66];

    const int tid = threadIdx.x;
    const int bx = blockIdx.x, by = blockIdx.y, b = blockIdx.z;
    const int lx = tid & 31, ly = tid >> 5;
    const int xg0 = bx*64 + lx;
    const int yg = by*8 + ly;

    for (int t = tid; t < CC*9*OFFC/4; t += 256)
        ((float4*)wsm)[t] = ((const float4*)g_offwT)[t];

    float acc[OFFC][2];
    #pragma unroll
    for (int o = 0; o < OFFC; ++o) { float bv = off_b[o]; acc[o][0] = bv; acc[o][1] = bv; }

    const float* xb = x + (size_t)b*CC*HWX;

    #pragma unroll 1
    for (int c = 0; c < CC; ++c) {
        __syncthreads();
        for (int t = tid; t < 660; t += 256) {
            int r = t / 66, q = t % 66;
            int gy = by*8 + r - 1, gx = bx*64 + q - 1;
            float v = 0.f;
            if (gy >= 0 && gy < HH && gx >= 0 && gx < WW)
                v = xb[c*HWX + gy*WW + gx];
            xs[t] = v;
        }
        __syncthreads();
        const float* wc = wsm + c*9*OFFC;
        #pragma unroll
        for (int t = 0; t < 9; ++t) {
            int i = t/3, j = t%3;
            float xa  = xs[(ly+i)*66 + lx + j];
            float xc2 = xs[(ly+i)*66 + lx + 32 + j];
            const float2* w2 = (const float2*)(wc + t*OFFC);
            #pragma unroll
            for (int o2 = 0; o2 < 9; ++o2) {
                float2 w = w2[o2];
                acc[2*o2  ][0] += w.x*xa; acc[2*o2  ][1] += w.x*xc2;
                acc[2*o2+1][0] += w.y*xa; acc[2*o2+1][1] += w.y*xc2;
            }
        }
    }
    #pragma unroll
    for (int o = 0; o < OFFC; ++o) {
        g_off[((b*OFFC + o)*HH + yg)*WW + xg0     ] = acc[o][0];
        g_off[((b*OFFC + o)*HH + yg)*WW + xg0 + 32] = acc[o][1];
    }
}

// ---------------------------------------------------------------------------
// K2: deformable 3x3 conv 64->64 + BatchNorm + fused global-pool partial sums
// block = 1 row x 64 px, all 64 out channels; 256 threads.
// Thread: 4 outch (og=tid>>4) x 4 px (pq=tid&15), channel-paired FFMA2.
// Samples in smem as [c2][2*px+parity]; accumulators = 16 u64 = 32 regs.
// grid (3, 192, 4); dynamic smem 33.3 KB
// ---------------------------------------------------------------------------
__global__ __launch_bounds__(256) void deform_bn_kernel(
        const float* __restrict__ x,
        const float* __restrict__ db,
        const float* __restrict__ gma,
        const float* __restrict__ bta,
        const float* __restrict__ mean,
        const float* __restrict__ var) {
    extern __shared__ __align__(16) float smem[];
    float* dw_s   = smem + DW_S_OFF;     // one tap [o][c]: 16 KB
    float* samp_s = smem + SAMP_S_OFF;   // [c2][2*px+par], pitch 132

    const int tid = threadIdx.x;
    const int b   = blockIdx.z;
    const int y   = blockIdx.y;
    const int x0b = blockIdx.x * 64;
    const int pq  = tid & 15;        // pixel quad: px 4pq..4pq+3
    const int og  = tid >> 4;        // outch group: o = og*4..og*4+3
    const int ppg = tid & 63;        // gather pixel 0..63
    const int cgr = tid >> 6;        // gather c2 subgroup 0..3 (c2 = cgr*8+r)

    const float* xb = x + (size_t)b*CC*HWX;

    // fixed gather-pixel coordinates for this thread
    const int xx = x0b + ppg;
    const float* offpix = g_off + (size_t)b*OFFC*HWX + y*WW + xx;

    u64 acc2[4][4];
    #pragma unroll
    for (int r = 0; r < 4; ++r)
        #pragma unroll
        for (int p = 0; p < 4; ++p) acc2[r][p] = 0ull;

    #pragma unroll 1
    for (int kk = 0; kk < 9; ++kk) {
        const int i = kk/3, j = kk%3;
        // ---- per-tap bilinear metadata in registers ----
        float oy = offpix[(2*kk  )*HWX];
        float ox = offpix[(2*kk+1)*HWX];
        float py = (float)(y  + i - 1) + oy;
        float px = (float)(xx + j - 1) + ox;
        float fy = floorf(py), fx = floorf(px);
        int yq = (int)fy, xq = (int)fx;
        float wy = py - fy, wx = px - fx;
        float vy0 = ((unsigned)yq     < (unsigned)HH) ? 1.f : 0.f;
        float vy1 = ((unsigned)(yq+1) < (unsigned)HH) ? 1.f : 0.f;
        float vx0 = ((unsigned)xq     < (unsigned)WW) ? 1.f : 0.f;
        float vx1 = ((unsigned)(xq+1) < (unsigned)WW) ? 1.f : 0.f;
        float w00 = (1.f-wy)*(1.f-wx)*vy0*vx0;
        float w01 = (1.f-wy)*wx      *vy0*vx1;
        float w10 = wy*(1.f-wx)      *vy1*vx0;
        float w11 = wy*wx            *vy1*vx1;
        int yc0 = min(max(yq,   0), HH-1);
        int yc1 = min(max(yq+1, 0), HH-1);
        int xc0 = min(max(xq,   0), WW-1);
        int xc1 = min(max(xq+1, 0), WW-1);
        int o00 = yc0*WW + xc0, o01 = yc0*WW + xc1;
        int o10 = yc1*WW + xc0, o11 = yc1*WW + xc1;

        // ---- gather: 8 channel-pairs (c2 = cgr*8 + r) for this pixel ----
        {
            const float* xe = xb + (size_t)(2*(cgr*8))*HWX;
            float* sp = samp_s + (cgr*8)*SAMP_PITCH + 2*ppg;
            #pragma unroll
            for (int r = 0; r < 8; ++r) {
                const float* xo = xe + HWX;
                float ve = w00*xe[o00] + w01*xe[o01] + w10*xe[o10] + w11*xe[o11];
                float vo = w00*xo[o00] + w01*xo[o01] + w10*xo[o10] + w11*xo[o11];
                *(float2*)sp = make_float2(ve, vo);   // STS.64, conflict-free
                sp += SAMP_PITCH;
                xe += 2*HWX;
            }
        }
        // ---- stage this tap's weights (coalesced, pre-transposed [o][c]) ----
        for (int t = tid; t < 1024; t += 256)
            ((float4*)dw_s)[t] = ((const float4*)g_dwT)[kk*1024 + t];
        __syncthreads();

        // ---- channel-paired FFMA2 GEMM ----
        const ulonglong2* dwv = (const ulonglong2*)dw_s;
        #pragma unroll 4
        for (int c4 = 0; c4 < 16; ++c4) {
            // samples for c2 = 2c4 and 2c4+1, pixels 4pq..4pq+3
            const ulonglong2* sap = (const ulonglong2*)&samp_s[(2*c4  )*SAMP_PITCH + 8*pq];
            const ulonglong2* sbp = (const ulonglong2*)&samp_s[(2*c4+1)*SAMP_PITCH + 8*pq];
            ulonglong2 sa01 = sap[0], sa23 = sap[1];   // (px0,px1),(px2,px3) pairs
            ulonglong2 sb01 = sbp[0], sb23 = sbp[1];
            #pragma unroll
            for (int r = 0; r < 4; ++r) {
                ulonglong2 w = dwv[(og*4 + r)*16 + c4]; // .x=(w_e,w_o)@2c4 .y=@2c4+1
                FMA2(acc2[r][0], w.x, sa01.x);
                FMA2(acc2[r][1], w.x, sa01.y);
                FMA2(acc2[r][2], w.x, sa23.x);
                FMA2(acc2[r][3], w.x, sa23.y);
                FMA2(acc2[r][0], w.y, sb01.x);
                FMA2(acc2[r][1], w.y, sb01.y);
                FMA2(acc2[r][2], w.y, sb23.x);
                FMA2(acc2[r][3], w.y, sb23.y);
            }
        }
        __syncthreads();
    }

    // epilogue: combine lanes, bias, BN, store, fused pool partial sums
    #pragma unroll
    for (int r = 0; r < 4; ++r) {
        int o = og*4 + r;
        float inv = rsqrtf(var[o] + 1e-5f);
        float sc = gma[o]*inv, mu = mean[o], bt = bta[o], bv = db[o];
        float4 v; float lo, hi;
        UNPK(lo, hi, acc2[r][0]); v.x = (lo + hi + bv - mu)*sc + bt;
        UNPK(lo, hi, acc2[r][1]); v.y = (lo + hi + bv - mu)*sc + bt;
        UNPK(lo, hi, acc2[r][2]); v.z = (lo + hi + bv - mu)*sc + bt;
        UNPK(lo, hi, acc2[r][3]); v.w = (lo + hi + bv - mu)*sc + bt;
        *(float4*)&g_h[((b*CC + o)*HH + y)*WW + x0b + 4*pq] = v;
        // reduce over the 16 lanes sharing this og (pq 0..15)
        float s = (v.x + v.y) + (v.z + v.w);
        #pragma unroll
        for (int off = 8; off > 0; off >>= 1)
            s += __shfl_xor_sync(0xffffffffu, s, off);
        if (pq == 0) atomicAdd(&g_pool[b*CC + o], s);
    }
}

// ---------------------------------------------------------------------------
// K3: SE MLP (hid=4): one block (scales pooled sums by 1/HW)
// ---------------------------------------------------------------------------
__global__ __launch_bounds__(256) void ca_kernel(
        const float* __restrict__ w1, const float* __restrict__ b1,
        const float* __restrict__ w2, const float* __restrict__ b2) {
    __shared__ float t[BB*HID];
    const int tid = threadIdx.x;
    const int b = tid >> 6, c = tid & 63;
    if (c < HID) {
        float s = b1[c];
        for (int cc = 0; cc < CC; ++cc)
            s += w1[c*CC + cc] * (g_pool[b*CC + cc] * (1.f/(float)HWX));
        t[b*HID + c] = fmaxf(s, 0.f);
    }
    __syncthreads();
    float s = b2[c];
    #pragma unroll
    for (int h = 0; h < HID; ++h) s += w2[c*HID + h] * t[b*HID + h];
    g_cw[tid] = 1.f / (1.f + expf(-s));
}

// ---------------------------------------------------------------------------
// K4: spatial attention 7x7 conv -> sigmoid -> fused final output
// tile 64x8, 256 threads, 2 pixels/thread (x and x+32); grid (3, 24, 4)
// ---------------------------------------------------------------------------
__global__ __launch_bounds__(256) void sa_final_kernel(
        const float* __restrict__ sa_w, const float* __restrict__ sa_b,
        float* __restrict__ out) {
    __shared__ float ws[CC*49];
    __shared__ float xs[14*70];
    __shared__ float cws[CC];
    const int tid = threadIdx.x;
    const int bx = blockIdx.x, by = blockIdx.y, b = blockIdx.z;
    const int lx = tid & 31, ly = tid >> 5;
    const int xg0 = bx*64 + lx, yg = by*8 + ly;

    for (int t = tid; t < CC*49; t += 256) ws[t] = sa_w[t];
    if (tid < CC) cws[tid] = g_cw[b*CC + tid];

    float acc0 = sa_b[0], acc1 = sa_b[0];
    const float* hb = g_h + (size_t)b*CC*HWX;

    #pragma unroll 1
    for (int c = 0; c < CC; ++c) {
        __syncthreads();
        for (int t = tid; t < 14*70; t += 256) {
            int r = t / 70, q = t % 70;
            int gy = by*8 + r - 3, gx = bx*64 + q - 3;
            float v = 0.f;
            if (gy >= 0 && gy < HH && gx >= 0 && gx < WW)
                v = hb[c*HWX + gy*WW + gx];
            xs[t] = v;
        }
        __syncthreads();
        float s0 = 0.f, s1 = 0.f;
        #pragma unroll
        for (int dy = 0; dy < 7; ++dy) {
            #pragma unroll
            for (int dx = 0; dx < 7; ++dx) {
                float w = ws[c*49 + dy*7 + dx];
                s0 += xs[(ly+dy)*70 + lx + dx     ] * w;
                s1 += xs[(ly+dy)*70 + lx + 32 + dx] * w;
            }
        }
        acc0 += s0 * cws[c];
        acc1 += s1 * cws[c];
    }
    float sw0 = 1.f / (1.f + expf(-acc0));
    float sw1 = 1.f / (1.f + expf(-acc1));

    // fused finalize: out = h * cw * sw for all 64 channels of this tile
    const int base = yg*WW + xg0;
    #pragma unroll 4
    for (int c = 0; c < CC; ++c) {
        float cw = cws[c];
        float h0 = hb[c*HWX + base];
        float h1 = hb[c*HWX + base + 32];
        out[((size_t)(b*CC + c))*HWX + base     ] = h0*cw*sw0;
        out[((size_t)(b*CC + c))*HWX + base + 32] = h1*cw*sw1;
    }
}

// ---------------------------------------------------------------------------
extern "C" void kernel_launch(void* const* d_in, const int* in_sizes, int n_in,
                              void* d_out, int out_size) {
    const float* x      = (const float*)d_in[0];
    const float* off_w  = (const float*)d_in[1];
    const float* off_b  = (const float*)d_in[2];
    const float* dw     = (const float*)d_in[3];
    const float* db     = (const float*)d_in[4];
    const float* bn_g   = (const float*)d_in[5];
    const float* bn_b   = (const float*)d_in[6];
    const float* bn_m   = (const float*)d_in[7];
    const float* bn_v   = (const float*)d_in[8];
    const float* ca_w1  = (const float*)d_in[9];
    const float* ca_b1  = (const float*)d_in[10];
    const float* ca_w2  = (const float*)d_in[11];
    const float* ca_b2  = (const float*)d_in[12];
    const float* sa_w   = (const float*)d_in[13];
    const float* sa_b   = (const float*)d_in[14];
    float* out = (float*)d_out;

    cudaFuncSetAttribute(deform_bn_kernel,
                         cudaFuncAttributeMaxDynamicSharedMemorySize,
                         DEFORM_SMEM_BYTES);

    transpose_w_kernel<<<(9*CC*CC + CC*9*OFFC + 255)/256, 256>>>(dw, off_w);
    offset_conv_kernel<<<dim3(WW/64, HH/8, BB), 256>>>(x, off_b);
    deform_bn_kernel  <<<dim3(WW/64, HH, BB), 256, DEFORM_SMEM_BYTES>>>(
                          x, db, bn_g, bn_b, bn_m, bn_v);
    ca_kernel         <<<1, 256>>>(ca_w1, ca_b1, ca_w2, ca_b2);
    sa_final_kernel   <<<dim3(WW/64, HH/8, BB), 256>>>(sa_w, sa_b, out);
}

// round 9
// speedup vs baseline: 1.4922x; 1.4922x over previous
#include <cuda_runtime.h>
#include <math.h>
#include <stdint.h>

#define BB   4
#define CC   64
#define HH   192
#define WW   192
#define HWX  (HH*WW)
#define OFFC 18
#define HID  4

__device__ __forceinline__ uint32_t f2tf32(float f) {
    uint32_t r;
    asm("cvt.rna.tf32.f32 %0, %1;" : "=r"(r) : "f"(f));
    return r;
}

// warp-level tf32 MMA: D(16x8) += A(16x8) * B(8x8), fp32 accumulate
#define MMA_TF32(d0,d1,d2,d3, a0,a1,a2,a3, b0,b1)                              \
    asm volatile("mma.sync.aligned.m16n8k8.row.col.f32.tf32.tf32.f32 "         \
        "{%0,%1,%2,%3}, {%4,%5,%6,%7}, {%8,%9}, {%0,%1,%2,%3};"                \
        : "+f"(d0), "+f"(d1), "+f"(d2), "+f"(d3)                               \
        : "r"(a0), "r"(a1), "r"(a2), "r"(a3), "r"(b0), "r"(b1))

// scratch (device globals; allocations are forbidden)
__device__ float g_off[BB*OFFC*HH*WW];        // 10.6 MB
__device__ float g_h  [BB*CC*HH*WW];          // 37.7 MB
__device__ float g_pool[BB*CC];               // post-BN channel sums
__device__ float g_cw  [BB*CC];
__device__ float g_dwT [9*CC*CC];             // [kk][o][c], tf32-rounded bits
__device__ float g_offwT[CC*9*OFFC];          // [(c*9+t)*18 + o]

// deform dynamic smem layout (floats)
#define PITCH    68
#define SCS_OFF  0                             // 64: gamma*rsqrt(var+eps)
#define SHS_OFF  64                            // 64: (db-mean)*sc + beta
#define A_OFF    128                           // A: [128][PITCH] tf32 samples
#define B_OFF    (A_OFF + 128*PITCH)           // B: [64][PITCH] tf32 weights
#define DEFORM_SMEM_FLOATS (B_OFF + 64*PITCH)
#define DEFORM_SMEM_BYTES  (DEFORM_SMEM_FLOATS*4)   // 52736 B

// ---------------------------------------------------------------------------
// K0: weight prep (deform weights tf32-rounded + transposed; offset weights)
// ---------------------------------------------------------------------------
__global__ __launch_bounds__(256) void transpose_w_kernel(
        const float* __restrict__ dw, const float* __restrict__ off_w) {
    int d = blockIdx.x*256 + threadIdx.x;
    if (blockIdx.x == 0) g_pool[threadIdx.x] = 0.f;
    if (d < 9*CC*CC) {
        int kk = d >> 12;
        int o  = (d >> 6) & 63;
        int c  = d & 63;
        g_dwT[d] = __uint_as_float(f2tf32(dw[(o*CC + c)*9 + kk]));
    } else {
        int e = d - 9*CC*CC;
        if (e < CC*9*OFFC) {
            int k = e / OFFC;      // c*9+t
            int o = e % OFFC;
            int c = k / 9, t = k % 9;
            g_offwT[e] = off_w[(o*CC + c)*9 + t];
        }
    }
}

// ---------------------------------------------------------------------------
// K1: 3x3 conv 64 -> 18 (offset prediction), pad 1  (R6, unchanged)
// ---------------------------------------------------------------------------
__global__ __launch_bounds__(256) void offset_conv_kernel(
        const float* __restrict__ x,
        const float* __restrict__ off_b) {
    __shared__ float wsm[CC*9*OFFC];
    __shared__ float xs[10*66];

    const int tid = threadIdx.x;
    const int bx = blockIdx.x, by = blockIdx.y, b = blockIdx.z;
    const int lx = tid & 31, ly = tid >> 5;
    const int xg0 = bx*64 + lx;
    const int yg = by*8 + ly;

    for (int t = tid; t < CC*9*OFFC/4; t += 256)
        ((float4*)wsm)[t] = ((const float4*)g_offwT)[t];

    float acc[OFFC][2];
    #pragma unroll
    for (int o = 0; o < OFFC; ++o) { float bv = off_b[o]; acc[o][0] = bv; acc[o][1] = bv; }

    const float* xb = x + (size_t)b*CC*HWX;

    #pragma unroll 1
    for (int c = 0; c < CC; ++c) {
        __syncthreads();
        for (int t = tid; t < 660; t += 256) {
            int r = t / 66, q = t % 66;
            int gy = by*8 + r - 1, gx = bx*64 + q - 1;
            float v = 0.f;
            if (gy >= 0 && gy < HH && gx >= 0 && gx < WW)
                v = xb[c*HWX + gy*WW + gx];
            xs[t] = v;
        }
        __syncthreads();
        const float* wc = wsm + c*9*OFFC;
        #pragma unroll
        for (int t = 0; t < 9; ++t) {
            int i = t/3, j = t%3;
            float xa  = xs[(ly+i)*66 + lx + j];
            float xc2 = xs[(ly+i)*66 + lx + 32 + j];
            const float2* w2 = (const float2*)(wc + t*OFFC);
            #pragma unroll
            for (int o2 = 0; o2 < 9; ++o2) {
                float2 w = w2[o2];
                acc[2*o2  ][0] += w.x*xa; acc[2*o2  ][1] += w.x*xc2;
                acc[2*o2+1][0] += w.y*xa; acc[2*o2+1][1] += w.y*xc2;
            }
        }
    }
    #pragma unroll
    for (int o = 0; o < OFFC; ++o) {
        g_off[((b*OFFC + o)*HH + yg)*WW + xg0     ] = acc[o][0];
        g_off[((b*OFFC + o)*HH + yg)*WW + xg0 + 32] = acc[o][1];
    }
}

// ---------------------------------------------------------------------------
// K2: deformable 3x3 conv 64->64 via mma.sync tf32 + BN + fused pool
// block = 2 rows x 64 px = 128 pixels (M), 64 outch (N); 256 threads (8 warps)
// Each warp: one 16-px M-tile x all 8 N-tiles; K = 64 per tap, 9 taps.
// grid (3, 96, 4); dynamic smem 52.7 KB
// ---------------------------------------------------------------------------
__global__ __launch_bounds__(256) void deform_bn_kernel(
        const float* __restrict__ x,
        const float* __restrict__ db,
        const float* __restrict__ gma,
        const float* __restrict__ bta,
        const float* __restrict__ mean,
        const float* __restrict__ var) {
    extern __shared__ __align__(16) float smem[];
    float* sc_s = smem + SCS_OFF;
    float* sh_s = smem + SHS_OFF;
    float* A_s  = smem + A_OFF;     // [128][PITCH] tf32 bits
    float* B_s  = smem + B_OFF;     // [64][PITCH]  tf32 bits

    const int tid = threadIdx.x;
    const int wid = tid >> 5;
    const int lid = tid & 31;
    const int b   = blockIdx.z;
    const int y0  = blockIdx.y * 2;
    const int x0b = blockIdx.x * 64;
    const int ppg = tid & 127;       // gather pixel 0..127
    const int hg  = tid >> 7;        // channel chunk 0..1 (c = hg*32..+31)

    if (tid < 64) {
        float sc = gma[tid] * rsqrtf(var[tid] + 1e-5f);
        sc_s[tid] = sc;
        sh_s[tid] = (db[tid] - mean[tid])*sc + bta[tid];
    }

    const float* xb = x + (size_t)b*CC*HWX;
    const int grow = ppg >> 6, gcol = ppg & 63;
    const int yy = y0 + grow, xx = x0b + gcol;
    const float* offpix = g_off + (size_t)b*OFFC*HWX + yy*WW + xx;

    // D fragments: 8 n-tiles x 4 regs
    float d0[8], d1[8], d2[8], d3[8];
    #pragma unroll
    for (int nt = 0; nt < 8; ++nt) { d0[nt]=0.f; d1[nt]=0.f; d2[nt]=0.f; d3[nt]=0.f; }

    #pragma unroll 1
    for (int kk = 0; kk < 9; ++kk) {
        const int i = kk/3, j = kk%3;
        // ---- per-tap bilinear metadata in registers ----
        float oy = offpix[(2*kk  )*HWX];
        float ox = offpix[(2*kk+1)*HWX];
        float py = (float)(yy + i - 1) + oy;
        float px = (float)(xx + j - 1) + ox;
        float fy = floorf(py), fx = floorf(px);
        int yq = (int)fy, xq = (int)fx;
        float wy = py - fy, wx = px - fx;
        float vy0 = ((unsigned)yq     < (unsigned)HH) ? 1.f : 0.f;
        float vy1 = ((unsigned)(yq+1) < (unsigned)HH) ? 1.f : 0.f;
        float vx0 = ((unsigned)xq     < (unsigned)WW) ? 1.f : 0.f;
        float vx1 = ((unsigned)(xq+1) < (unsigned)WW) ? 1.f : 0.f;
        float w00 = (1.f-wy)*(1.f-wx)*vy0*vx0;
        float w01 = (1.f-wy)*wx      *vy0*vx1;
        float w10 = wy*(1.f-wx)      *vy1*vx0;
        float w11 = wy*wx            *vy1*vx1;
        int yc0 = min(max(yq,   0), HH-1);
        int yc1 = min(max(yq+1, 0), HH-1);
        int xc0 = min(max(xq,   0), WW-1);
        int xc1 = min(max(xq+1, 0), WW-1);
        int o00 = yc0*WW + xc0, o01 = yc0*WW + xc1;
        int o10 = yc1*WW + xc0, o11 = yc1*WW + xc1;

        // ---- gather 32 channels for this pixel into A (tf32 bits) ----
        {
            uint32_t* arow = (uint32_t*)(A_s + ppg*PITCH + hg*32);
            const float* xc = xb + (size_t)(hg*32)*HWX;
            #pragma unroll 4
            for (int r = 0; r < 8; ++r) {
                uint4 pk;
                float v0 = w00*xc[o00] + w01*xc[o01] + w10*xc[o10] + w11*xc[o11]; xc += HWX;
                float v1 = w00*xc[o00] + w01*xc[o01] + w10*xc[o10] + w11*xc[o11]; xc += HWX;
                float v2 = w00*xc[o00] + w01*xc[o01] + w10*xc[o10] + w11*xc[o11]; xc += HWX;
                float v3 = w00*xc[o00] + w01*xc[o01] + w10*xc[o10] + w11*xc[o11]; xc += HWX;
                pk.x = f2tf32(v0); pk.y = f2tf32(v1); pk.z = f2tf32(v2); pk.w = f2tf32(v3);
                *(uint4*)(arow + r*4) = pk;   // STS.128, conflict-free
            }
        }
        // ---- stage this tap's weights into B [o][PITCH] ----
        {
            const float4* src = (const float4*)(g_dwT + kk*4096);
            for (int t = tid; t < 1024; t += 256) {
                int o = t >> 4, c4 = (t & 15) << 2;
                *(float4*)(B_s + o*PITCH + c4) = src[t];
            }
        }
        __syncthreads();

        // ---- warp MMA: Mtile = wid, all 8 n-tiles, 8 k-steps ----
        {
            const int row = wid*16 + (lid >> 2);
            const int klo = lid & 3;
            #pragma unroll
            for (int k = 0; k < 8; ++k) {
                const int col = k*8 + klo;
                uint32_t a0 = *(const uint32_t*)(A_s + row*PITCH + col);
                uint32_t a1 = *(const uint32_t*)(A_s + (row+8)*PITCH + col);
                uint32_t a2 = *(const uint32_t*)(A_s + row*PITCH + col + 4);
                uint32_t a3 = *(const uint32_t*)(A_s + (row+8)*PITCH + col + 4);
                #pragma unroll
                for (int nt = 0; nt < 8; ++nt) {
                    const int orow = nt*8 + (lid >> 2);
                    uint32_t b0 = *(const uint32_t*)(B_s + orow*PITCH + col);
                    uint32_t b1 = *(const uint32_t*)(B_s + orow*PITCH + col + 4);
                    MMA_TF32(d0[nt], d1[nt], d2[nt], d3[nt], a0, a1, a2, a3, b0, b1);
                }
            }
        }
        __syncthreads();
    }

    // ---- epilogue: BN, store, fused pool partial sums ----
    {
        const int p0 = wid*16 + (lid >> 2);     // pixel row of c0/c1
        const int p1 = p0 + 8;                  // pixel row of c2/c3
        const int y0p = y0 + (p0 >> 6), x0p = x0b + (p0 & 63);
        const int y1p = y0 + (p1 >> 6), x1p = x0b + (p1 & 63);
        const size_t hb0 = ((size_t)b*CC)*HWX + (size_t)y0p*WW + x0p;
        const size_t hb1 = ((size_t)b*CC)*HWX + (size_t)y1p*WW + x1p;
        #pragma unroll
        for (int nt = 0; nt < 8; ++nt) {
            int o0 = nt*8 + (lid & 3)*2;
            int o1 = o0 + 1;
            float sc0 = sc_s[o0], sh0 = sh_s[o0];
            float sc1 = sc_s[o1], sh1 = sh_s[o1];
            float v00 = d0[nt]*sc0 + sh0;   // (p0, o0)
            float v01 = d1[nt]*sc1 + sh1;   // (p0, o1)
            float v10 = d2[nt]*sc0 + sh0;   // (p1, o0)
            float v11 = d3[nt]*sc1 + sh1;   // (p1, o1)
            g_h[hb0 + (size_t)o0*HWX] = v00;
            g_h[hb0 + (size_t)o1*HWX] = v01;
            g_h[hb1 + (size_t)o0*HWX] = v10;
            g_h[hb1 + (size_t)o1*HWX] = v11;
            float s0 = v00 + v10;   // channel o0 over this thread's 2 px
            float s1 = v01 + v11;   // channel o1
            #pragma unroll
            for (int off = 4; off < 32; off <<= 1) {
                s0 += __shfl_xor_sync(0xffffffffu, s0, off);
                s1 += __shfl_xor_sync(0xffffffffu, s1, off);
            }
            if ((lid >> 2) == 0) {
                atomicAdd(&g_pool[b*CC + o0], s0);
                atomicAdd(&g_pool[b*CC + o1], s1);
            }
        }
    }
}

// ---------------------------------------------------------------------------
// K3: SE MLP (hid=4): one block (scales pooled sums by 1/HW)
// ---------------------------------------------------------------------------
__global__ __launch_bounds__(256) void ca_kernel(
        const float* __restrict__ w1, const float* __restrict__ b1,
        const float* __restrict__ w2, const float* __restrict__ b2) {
    __shared__ float t[BB*HID];
    const int tid = threadIdx.x;
    const int b = tid >> 6, c = tid & 63;
    if (c < HID) {
        float s = b1[c];
        for (int cc = 0; cc < CC; ++cc)
            s += w1[c*CC + cc] * (g_pool[b*CC + cc] * (1.f/(float)HWX));
        t[b*HID + c] = fmaxf(s, 0.f);
    }
    __syncthreads();
    float s = b2[c];
    #pragma unroll
    for (int h = 0; h < HID; ++h) s += w2[c*HID + h] * t[b*HID + h];
    g_cw[tid] = 1.f / (1.f + expf(-s));
}

// ---------------------------------------------------------------------------
// K4: spatial attention 7x7 conv -> sigmoid -> fused final output (R6)
// ---------------------------------------------------------------------------
__global__ __launch_bounds__(256) void sa_final_kernel(
        const float* __restrict__ sa_w, const float* __restrict__ sa_b,
        float* __restrict__ out) {
    __shared__ float ws[CC*49];
    __shared__ float xs[14*70];
    __shared__ float cws[CC];
    const int tid = threadIdx.x;
    const int bx = blockIdx.x, by = blockIdx.y, b = blockIdx.z;
    const int lx = tid & 31, ly = tid >> 5;
    const int xg0 = bx*64 + lx, yg = by*8 + ly;

    for (int t = tid; t < CC*49; t += 256) ws[t] = sa_w[t];
    if (tid < CC) cws[tid] = g_cw[b*CC + tid];

    float acc0 = sa_b[0], acc1 = sa_b[0];
    const float* hb = g_h + (size_t)b*CC*HWX;

    #pragma unroll 1
    for (int c = 0; c < CC; ++c) {
        __syncthreads();
        for (int t = tid; t < 14*70; t += 256) {
            int r = t / 70, q = t % 70;
            int gy = by*8 + r - 3, gx = bx*64 + q - 3;
            float v = 0.f;
            if (gy >= 0 && gy < HH && gx >= 0 && gx < WW)
                v = hb[c*HWX + gy*WW + gx];
            xs[t] = v;
        }
        __syncthreads();
        float s0 = 0.f, s1 = 0.f;
        #pragma unroll
        for (int dy = 0; dy < 7; ++dy) {
            #pragma unroll
            for (int dx = 0; dx < 7; ++dx) {
                float w = ws[c*49 + dy*7 + dx];
                s0 += xs[(ly+dy)*70 + lx + dx     ] * w;
                s1 += xs[(ly+dy)*70 + lx + 32 + dx] * w;
            }
        }
        acc0 += s0 * cws[c];
        acc1 += s1 * cws[c];
    }
    float sw0 = 1.f / (1.f + expf(-acc0));
    float sw1 = 1.f / (1.f + expf(-acc1));

    const int base = yg*WW + xg0;
    #pragma unroll 4
    for (int c = 0; c < CC; ++c) {
        float cw = cws[c];
        float h0 = hb[c*HWX + base];
        float h1 = hb[c*HWX + base + 32];
        out[((size_t)(b*CC + c))*HWX + base     ] = h0*cw*sw0;
        out[((size_t)(b*CC + c))*HWX + base + 32] = h1*cw*sw1;
    }
}

// ---------------------------------------------------------------------------
extern "C" void kernel_launch(void* const* d_in, const int* in_sizes, int n_in,
                              void* d_out, int out_size) {
    const float* x      = (const float*)d_in[0];
    const float* off_w  = (const float*)d_in[1];
    const float* off_b  = (const float*)d_in[2];
    const float* dw     = (const float*)d_in[3];
    const float* db     = (const float*)d_in[4];
    const float* bn_g   = (const float*)d_in[5];
    const float* bn_b   = (const float*)d_in[6];
    const float* bn_m   = (const float*)d_in[7];
    const float* bn_v   = (const float*)d_in[8];
    const float* ca_w1  = (const float*)d_in[9];
    const float* ca_b1  = (const float*)d_in[10];
    const float* ca_w2  = (const float*)d_in[11];
    const float* ca_b2  = (const float*)d_in[12];
    const float* sa_w   = (const float*)d_in[13];
    const float* sa_b   = (const float*)d_in[14];
    float* out = (float*)d_out;

    cudaFuncSetAttribute(deform_bn_kernel,
                         cudaFuncAttributeMaxDynamicSharedMemorySize,
                         DEFORM_SMEM_BYTES);

    transpose_w_kernel<<<(9*CC*CC + CC*9*OFFC + 255)/256, 256>>>(dw, off_w);
    offset_conv_kernel<<<dim3(WW/64, HH/8, BB), 256>>>(x, off_b);
    deform_bn_kernel  <<<dim3(WW/64, HH/2, BB), 256, DEFORM_SMEM_BYTES>>>(
                          x, db, bn_g, bn_b, bn_m, bn_v);
    ca_kernel         <<<1, 256>>>(ca_w1, ca_b1, ca_w2, ca_b2);
    sa_final_kernel   <<<dim3(WW/64, HH/8, BB), 256>>>(sa_w, sa_b, out);
}

// round 10
// speedup vs baseline: 1.8136x; 1.2154x over previous
#include <cuda_runtime.h>
#include <math.h>
#include <stdint.h>

#define BB   4
#define CC   64
#define HH   192
#define WW   192
#define HWX  (HH*WW)
#define OFFC 18
#define HID  4

__device__ __forceinline__ uint32_t f2tf32(float f) {
    uint32_t r;
    asm("cvt.rna.tf32.f32 %0, %1;" : "=r"(r) : "f"(f));
    return r;
}

// warp-level tf32 MMA: D(16x8) += A(16x8) * B(8x8), fp32 accumulate
#define MMA_TF32(d0,d1,d2,d3, a0,a1,a2,a3, b0,b1)                              \
    asm volatile("mma.sync.aligned.m16n8k8.row.col.f32.tf32.tf32.f32 "         \
        "{%0,%1,%2,%3}, {%4,%5,%6,%7}, {%8,%9}, {%0,%1,%2,%3};"                \
        : "+f"(d0), "+f"(d1), "+f"(d2), "+f"(d3)                               \
        : "r"(a0), "r"(a1), "r"(a2), "r"(a3), "r"(b0), "r"(b1))

// scratch (device globals; allocations are forbidden)
__device__ float g_off[BB*OFFC*HH*WW];        // 10.6 MB
__device__ float g_h  [BB*CC*HH*WW];          // 37.7 MB
__device__ float g_pool[BB*CC];               // post-BN channel sums
__device__ float g_cw  [BB*CC];
__device__ float g_dwT [9*CC*CC];             // [kk][o][c], tf32-rounded bits
__device__ uint32_t g_offwB[8*24*76];         // [chunk][o(pad24)][tap*8+cc pad76]

// deform dynamic smem layout (floats)  -- identical to R9
#define PITCH    68
#define SCS_OFF  0
#define SHS_OFF  64
#define A_OFF    128
#define B_OFF    (A_OFF + 128*PITCH)
#define DEFORM_SMEM_FLOATS (B_OFF + 64*PITCH)
#define DEFORM_SMEM_BYTES  (DEFORM_SMEM_FLOATS*4)   // 52736 B

// ---------------------------------------------------------------------------
// K0: weight prep (deform weights tf32+transposed; offset weights -> B panels)
// ---------------------------------------------------------------------------
__global__ __launch_bounds__(256) void transpose_w_kernel(
        const float* __restrict__ dw, const float* __restrict__ off_w) {
    int d = blockIdx.x*256 + threadIdx.x;
    if (blockIdx.x == 0) g_pool[threadIdx.x] = 0.f;
    if (d < 9*CC*CC) {
        int kk = d >> 12;
        int o  = (d >> 6) & 63;
        int c  = d & 63;
        g_dwT[d] = __uint_as_float(f2tf32(dw[(o*CC + c)*9 + kk]));
    } else {
        int e = d - 9*CC*CC;
        if (e < 8*24*76) {
            int c8  = e / (24*76);
            int rem = e % (24*76);
            int o   = rem / 76;
            int col = rem % 76;
            int tap = col >> 3, cc = col & 7;
            uint32_t v = 0u;
            if (o < OFFC && col < 72)
                v = f2tf32(off_w[(o*CC + c8*8 + cc)*9 + tap]);
            g_offwB[e] = v;
        }
    }
}

// ---------------------------------------------------------------------------
// K1: 3x3 conv 64 -> 18 via mma.sync tf32.
// tile 64x8 = 512 px (M), 18->24 outch (N), K=576 in 8 chunks of 72.
// 256 threads; warp wid owns image row wid of the tile (4 m-tiles).
// grid (3, 24, 4); static smem 29 KB
// ---------------------------------------------------------------------------
__global__ __launch_bounds__(256) void offset_conv_kernel(
        const float* __restrict__ x,
        const float* __restrict__ off_b) {
    __shared__ uint32_t halo[8*680];   // 8 ch planes (10x66, plane stride 680)
    __shared__ uint32_t B_s[24*76];

    const int tid = threadIdx.x;
    const int wid = tid >> 5, lid = tid & 31;
    const int bx = blockIdx.x, by = blockIdx.y, b = blockIdx.z;
    const int klo = lid & 3, r = lid >> 2;

    float d0[4][3], d1[4][3], d2[4][3], d3[4][3];
    #pragma unroll
    for (int q = 0; q < 4; ++q)
        #pragma unroll
        for (int nt = 0; nt < 3; ++nt)
            { d0[q][nt]=0.f; d1[q][nt]=0.f; d2[q][nt]=0.f; d3[q][nt]=0.f; }

    const float* xb = x + (size_t)b*CC*HWX;

    #pragma unroll 1
    for (int c8 = 0; c8 < 8; ++c8) {
        __syncthreads();
        // stage 8-channel halo (10x66 each), tf32 bits
        for (int t = tid; t < 5280; t += 256) {
            int ch = t / 660, rem = t % 660;
            int rr = rem / 66, q = rem % 66;
            int gy = by*8 + rr - 1, gx = bx*64 + q - 1;
            float v = 0.f;
            if (gy >= 0 && gy < HH && gx >= 0 && gx < WW)
                v = xb[(c8*8 + ch)*HWX + gy*WW + gx];
            halo[ch*680 + rr*66 + q] = f2tf32(v);
        }
        // stage B panel (pre-transposed, pre-padded, tf32)
        {
            const uint4* src = (const uint4*)(g_offwB + c8*24*76);
            uint4* dst = (uint4*)B_s;
            for (int t = tid; t < 456; t += 256) dst[t] = src[t];
        }
        __syncthreads();

        #pragma unroll
        for (int tap = 0; tap < 9; ++tap) {
            const int i = tap/3, j = tap%3;
            uint32_t b0[3], b1[3];
            #pragma unroll
            for (int nt = 0; nt < 3; ++nt) {
                b0[nt] = B_s[(nt*8 + r)*76 + tap*8 + klo];
                b1[nt] = B_s[(nt*8 + r)*76 + tap*8 + klo + 4];
            }
            #pragma unroll
            for (int q = 0; q < 4; ++q) {
                int a_idx = klo*680 + (wid + i)*66 + q*16 + r + j;
                uint32_t a0 = halo[a_idx];
                uint32_t a1 = halo[a_idx + 8];
                uint32_t a2 = halo[a_idx + 4*680];
                uint32_t a3 = halo[a_idx + 4*680 + 8];
                #pragma unroll
                for (int nt = 0; nt < 3; ++nt)
                    MMA_TF32(d0[q][nt], d1[q][nt], d2[q][nt], d3[q][nt],
                             a0, a1, a2, a3, b0[nt], b1[nt]);
            }
        }
    }

    // epilogue: add bias, write offsets
    const int yg = by*8 + wid;
    #pragma unroll
    for (int q = 0; q < 4; ++q) {
        int px0 = bx*64 + q*16 + r;
        #pragma unroll
        for (int nt = 0; nt < 3; ++nt) {
            int o0 = nt*8 + 2*klo, o1 = o0 + 1;
            if (o0 < OFFC) {
                float bv = off_b[o0];
                float* dst = &g_off[((size_t)(b*OFFC + o0)*HH + yg)*WW + px0];
                dst[0] = d0[q][nt] + bv;
                dst[8] = d2[q][nt] + bv;
            }
            if (o1 < OFFC) {
                float bv = off_b[o1];
                float* dst = &g_off[((size_t)(b*OFFC + o1)*HH + yg)*WW + px0];
                dst[0] = d1[q][nt] + bv;
                dst[8] = d3[q][nt] + bv;
            }
        }
    }
}

// ---------------------------------------------------------------------------
// K2: deformable 3x3 conv 64->64 via mma.sync tf32 + BN + fused pool
// (identical to R9, validated)
// ---------------------------------------------------------------------------
__global__ __launch_bounds__(256) void deform_bn_kernel(
        const float* __restrict__ x,
        const float* __restrict__ db,
        const float* __restrict__ gma,
        const float* __restrict__ bta,
        const float* __restrict__ mean,
        const float* __restrict__ var) {
    extern __shared__ __align__(16) float smem[];
    float* sc_s = smem + SCS_OFF;
    float* sh_s = smem + SHS_OFF;
    float* A_s  = smem + A_OFF;
    float* B_s  = smem + B_OFF;

    const int tid = threadIdx.x;
    const int wid = tid >> 5;
    const int lid = tid & 31;
    const int b   = blockIdx.z;
    const int y0  = blockIdx.y * 2;
    const int x0b = blockIdx.x * 64;
    const int ppg = tid & 127;
    const int hg  = tid >> 7;

    if (tid < 64) {
        float sc = gma[tid] * rsqrtf(var[tid] + 1e-5f);
        sc_s[tid] = sc;
        sh_s[tid] = (db[tid] - mean[tid])*sc + bta[tid];
    }

    const float* xb = x + (size_t)b*CC*HWX;
    const int grow = ppg >> 6, gcol = ppg & 63;
    const int yy = y0 + grow, xx = x0b + gcol;
    const float* offpix = g_off + (size_t)b*OFFC*HWX + yy*WW + xx;

    float d0[8], d1[8], d2[8], d3[8];
    #pragma unroll
    for (int nt = 0; nt < 8; ++nt) { d0[nt]=0.f; d1[nt]=0.f; d2[nt]=0.f; d3[nt]=0.f; }

    #pragma unroll 1
    for (int kk = 0; kk < 9; ++kk) {
        const int i = kk/3, j = kk%3;
        float oy = offpix[(2*kk  )*HWX];
        float ox = offpix[(2*kk+1)*HWX];
        float py = (float)(yy + i - 1) + oy;
        float px = (float)(xx + j - 1) + ox;
        float fy = floorf(py), fx = floorf(px);
        int yq = (int)fy, xq = (int)fx;
        float wy = py - fy, wx = px - fx;
        float vy0 = ((unsigned)yq     < (unsigned)HH) ? 1.f : 0.f;
        float vy1 = ((unsigned)(yq+1) < (unsigned)HH) ? 1.f : 0.f;
        float vx0 = ((unsigned)xq     < (unsigned)WW) ? 1.f : 0.f;
        float vx1 = ((unsigned)(xq+1) < (unsigned)WW) ? 1.f : 0.f;
        float w00 = (1.f-wy)*(1.f-wx)*vy0*vx0;
        float w01 = (1.f-wy)*wx      *vy0*vx1;
        float w10 = wy*(1.f-wx)      *vy1*vx0;
        float w11 = wy*wx            *vy1*vx1;
        int yc0 = min(max(yq,   0), HH-1);
        int yc1 = min(max(yq+1, 0), HH-1);
        int xc0 = min(max(xq,   0), WW-1);
        int xc1 = min(max(xq+1, 0), WW-1);
        int o00 = yc0*WW + xc0, o01 = yc0*WW + xc1;
        int o10 = yc1*WW + xc0, o11 = yc1*WW + xc1;

        {
            uint32_t* arow = (uint32_t*)(A_s + ppg*PITCH + hg*32);
            const float* xc = xb + (size_t)(hg*32)*HWX;
            #pragma unroll 4
            for (int r = 0; r < 8; ++r) {
                uint4 pk;
                float v0 = w00*xc[o00] + w01*xc[o01] + w10*xc[o10] + w11*xc[o11]; xc += HWX;
                float v1 = w00*xc[o00] + w01*xc[o01] + w10*xc[o10] + w11*xc[o11]; xc += HWX;
                float v2 = w00*xc[o00] + w01*xc[o01] + w10*xc[o10] + w11*xc[o11]; xc += HWX;
                float v3 = w00*xc[o00] + w01*xc[o01] + w10*xc[o10] + w11*xc[o11]; xc += HWX;
                pk.x = f2tf32(v0); pk.y = f2tf32(v1); pk.z = f2tf32(v2); pk.w = f2tf32(v3);
                *(uint4*)(arow + r*4) = pk;
            }
        }
        {
            const float4* src = (const float4*)(g_dwT + kk*4096);
            for (int t = tid; t < 1024; t += 256) {
                int o = t >> 4, c4 = (t & 15) << 2;
                *(float4*)(B_s + o*PITCH + c4) = src[t];
            }
        }
        __syncthreads();

        {
            const int row = wid*16 + (lid >> 2);
            const int klo = lid & 3;
            #pragma unroll
            for (int k = 0; k < 8; ++k) {
                const int col = k*8 + klo;
                uint32_t a0 = *(const uint32_t*)(A_s + row*PITCH + col);
                uint32_t a1 = *(const uint32_t*)(A_s + (row+8)*PITCH + col);
                uint32_t a2 = *(const uint32_t*)(A_s + row*PITCH + col + 4);
                uint32_t a3 = *(const uint32_t*)(A_s + (row+8)*PITCH + col + 4);
                #pragma unroll
                for (int nt = 0; nt < 8; ++nt) {
                    const int orow = nt*8 + (lid >> 2);
                    uint32_t b0 = *(const uint32_t*)(B_s + orow*PITCH + col);
                    uint32_t b1 = *(const uint32_t*)(B_s + orow*PITCH + col + 4);
                    MMA_TF32(d0[nt], d1[nt], d2[nt], d3[nt], a0, a1, a2, a3, b0, b1);
                }
            }
        }
        __syncthreads();
    }

    {
        const int p0 = wid*16 + (lid >> 2);
        const int p1 = p0 + 8;
        const int y0p = y0 + (p0 >> 6), x0p = x0b + (p0 & 63);
        const int y1p = y0 + (p1 >> 6), x1p = x0b + (p1 & 63);
        const size_t hb0 = ((size_t)b*CC)*HWX + (size_t)y0p*WW + x0p;
        const size_t hb1 = ((size_t)b*CC)*HWX + (size_t)y1p*WW + x1p;
        #pragma unroll
        for (int nt = 0; nt < 8; ++nt) {
            int o0 = nt*8 + (lid & 3)*2;
            int o1 = o0 + 1;
            float sc0 = sc_s[o0], sh0 = sh_s[o0];
            float sc1 = sc_s[o1], sh1 = sh_s[o1];
            float v00 = d0[nt]*sc0 + sh0;
            float v01 = d1[nt]*sc1 + sh1;
            float v10 = d2[nt]*sc0 + sh0;
            float v11 = d3[nt]*sc1 + sh1;
            g_h[hb0 + (size_t)o0*HWX] = v00;
            g_h[hb0 + (size_t)o1*HWX] = v01;
            g_h[hb1 + (size_t)o0*HWX] = v10;
            g_h[hb1 + (size_t)o1*HWX] = v11;
            float s0 = v00 + v10;
            float s1 = v01 + v11;
            #pragma unroll
            for (int off = 4; off < 32; off <<= 1) {
                s0 += __shfl_xor_sync(0xffffffffu, s0, off);
                s1 += __shfl_xor_sync(0xffffffffu, s1, off);
            }
            if ((lid >> 2) == 0) {
                atomicAdd(&g_pool[b*CC + o0], s0);
                atomicAdd(&g_pool[b*CC + o1], s1);
            }
        }
    }
}

// ---------------------------------------------------------------------------
// K3: SE MLP (hid=4)
// ---------------------------------------------------------------------------
__global__ __launch_bounds__(256) void ca_kernel(
        const float* __restrict__ w1, const float* __restrict__ b1,
        const float* __restrict__ w2, const float* __restrict__ b2) {
    __shared__ float t[BB*HID];
    const int tid = threadIdx.x;
    const int b = tid >> 6, c = tid & 63;
    if (c < HID) {
        float s = b1[c];
        for (int cc = 0; cc < CC; ++cc)
            s += w1[c*CC + cc] * (g_pool[b*CC + cc] * (1.f/(float)HWX));
        t[b*HID + c] = fmaxf(s, 0.f);
    }
    __syncthreads();
    float s = b2[c];
    #pragma unroll
    for (int h = 0; h < HID; ++h) s += w2[c*HID + h] * t[b*HID + h];
    g_cw[tid] = 1.f / (1.f + expf(-s));
}

// ---------------------------------------------------------------------------
// K4: spatial attention 7x7 conv -> sigmoid -> fused final output (R6)
// ---------------------------------------------------------------------------
__global__ __launch_bounds__(256) void sa_final_kernel(
        const float* __restrict__ sa_w, const float* __restrict__ sa_b,
        float* __restrict__ out) {
    __shared__ float ws[CC*49];
    __shared__ float xs[14*70];
    __shared__ float cws[CC];
    const int tid = threadIdx.x;
    const int bx = blockIdx.x, by = blockIdx.y, b = blockIdx.z;
    const int lx = tid & 31, ly = tid >> 5;
    const int xg0 = bx*64 + lx, yg = by*8 + ly;

    for (int t = tid; t < CC*49; t += 256) ws[t] = sa_w[t];
    if (tid < CC) cws[tid] = g_cw[b*CC + tid];

    float acc0 = sa_b[0], acc1 = sa_b[0];
    const float* hb = g_h + (size_t)b*CC*HWX;

    #pragma unroll 1
    for (int c = 0; c < CC; ++c) {
        __syncthreads();
        for (int t = tid; t < 14*70; t += 256) {
            int r = t / 70, q = t % 70;
            int gy = by*8 + r - 3, gx = bx*64 + q - 3;
            float v = 0.f;
            if (gy >= 0 && gy < HH && gx >= 0 && gx < WW)
                v = hb[c*HWX + gy*WW + gx];
            xs[t] = v;
        }
        __syncthreads();
        float s0 = 0.f, s1 = 0.f;
        #pragma unroll
        for (int dy = 0; dy < 7; ++dy) {
            #pragma unroll
            for (int dx = 0; dx < 7; ++dx) {
                float w = ws[c*49 + dy*7 + dx];
                s0 += xs[(ly+dy)*70 + lx + dx     ] * w;
                s1 += xs[(ly+dy)*70 + lx + 32 + dx] * w;
            }
        }
        acc0 += s0 * cws[c];
        acc1 += s1 * cws[c];
    }
    float sw0 = 1.f / (1.f + expf(-acc0));
    float sw1 = 1.f / (1.f + expf(-acc1));

    const int base = yg*WW + xg0;
    #pragma unroll 4
    for (int c = 0; c < CC; ++c) {
        float cw = cws[c];
        float h0 = hb[c*HWX + base];
        float h1 = hb[c*HWX + base + 32];
        out[((size_t)(b*CC + c))*HWX + base     ] = h0*cw*sw0;
        out[((size_t)(b*CC + c))*HWX + base + 32] = h1*cw*sw1;
    }
}

// ---------------------------------------------------------------------------
extern "C" void kernel_launch(void* const* d_in, const int* in_sizes, int n_in,
                              void* d_out, int out_size) {
    const float* x      = (const float*)d_in[0];
    const float* off_w  = (const float*)d_in[1];
    const float* off_b  = (const float*)d_in[2];
    const float* dw     = (const float*)d_in[3];
    const float* db     = (const float*)d_in[4];
    const float* bn_g   = (const float*)d_in[5];
    const float* bn_b   = (const float*)d_in[6];
    const float* bn_m   = (const float*)d_in[7];
    const float* bn_v   = (const float*)d_in[8];
    const float* ca_w1  = (const float*)d_in[9];
    const float* ca_b1  = (const float*)d_in[10];
    const float* ca_w2  = (const float*)d_in[11];
    const float* ca_b2  = (const float*)d_in[12];
    const float* sa_w   = (const float*)d_in[13];
    const float* sa_b   = (const float*)d_in[14];
    float* out = (float*)d_out;

    cudaFuncSetAttribute(deform_bn_kernel,
                         cudaFuncAttributeMaxDynamicSharedMemorySize,
                         DEFORM_SMEM_BYTES);

    transpose_w_kernel<<<(9*CC*CC + 8*24*76 + 255)/256, 256>>>(dw, off_w);
    offset_conv_kernel<<<dim3(WW/64, HH/8, BB), 256>>>(x, off_b);
    deform_bn_kernel  <<<dim3(WW/64, HH/2, BB), 256, DEFORM_SMEM_BYTES>>>(
                          x, db, bn_g, bn_b, bn_m, bn_v);
    ca_kernel         <<<1, 256>>>(ca_w1, ca_b1, ca_w2, ca_b2);
    sa_final_kernel   <<<dim3(WW/64, HH/8, BB), 256>>>(sa_w, sa_b, out);
}

// round 11
// speedup vs baseline: 1.8711x; 1.0317x over previous
#include <cuda_runtime.h>
#include <math.h>
#include <stdint.h>

#define BB   4
#define CC   64
#define HH   192
#define WW   192
#define HWX  (HH*WW)
#define OFFC 18
#define HID  4

__device__ __forceinline__ uint32_t f2tf32(float f) {
    uint32_t r;
    asm("cvt.rna.tf32.f32 %0, %1;" : "=r"(r) : "f"(f));
    return r;
}
__device__ __forceinline__ uint32_t fbits(float f) { return __float_as_uint(f); }

// warp-level tf32 MMA: D(16x8) += A(16x8) * B(8x8), fp32 accumulate
#define MMA_TF32(d0,d1,d2,d3, a0,a1,a2,a3, b0,b1)                              \
    asm volatile("mma.sync.aligned.m16n8k8.row.col.f32.tf32.tf32.f32 "         \
        "{%0,%1,%2,%3}, {%4,%5,%6,%7}, {%8,%9}, {%0,%1,%2,%3};"                \
        : "+f"(d0), "+f"(d1), "+f"(d2), "+f"(d3)                               \
        : "r"(a0), "r"(a1), "r"(a2), "r"(a3), "r"(b0), "r"(b1))

// scratch (device globals; allocations are forbidden)
__device__ float g_off[BB*OFFC*HH*WW];        // 10.6 MB
__device__ float g_h  [BB*CC*HH*WW];          // 37.7 MB
__device__ __align__(16) float g_xT[BB*HWX*CC]; // 37.7 MB  NHWC copy of x
__device__ float g_pool[BB*CC];
__device__ float g_cw  [BB*CC];
__device__ float g_dwT [9*CC*CC];             // [kk][o][c], tf32 bits
__device__ uint32_t g_offwB[8*24*76];         // offset-conv B panels

// deform dynamic smem layout (floats)
#define ABUF     4352                          // 64*68
#define SCS_OFF  0
#define SHS_OFF  64
#define A_OFF    128
#define B_OFF    (A_OFF + 2*ABUF)
#define M_OFF    (B_OFF + 2*ABUF)
#define DEFORM_SMEM_FLOATS (M_OFF + 2*512)
#define DEFORM_SMEM_BYTES  (DEFORM_SMEM_FLOATS*4)   // 74240 B -> 3 CTAs/SM

// ---------------------------------------------------------------------------
// K0: weight prep
// ---------------------------------------------------------------------------
__global__ __launch_bounds__(256) void transpose_w_kernel(
        const float* __restrict__ dw, const float* __restrict__ off_w) {
    int d = blockIdx.x*256 + threadIdx.x;
    if (blockIdx.x == 0) g_pool[threadIdx.x] = 0.f;
    if (d < 9*CC*CC) {
        int kk = d >> 12;
        int o  = (d >> 6) & 63;
        int c  = d & 63;
        g_dwT[d] = __uint_as_float(f2tf32(dw[(o*CC + c)*9 + kk]));
    } else {
        int e = d - 9*CC*CC;
        if (e < 8*24*76) {
            int c8  = e / (24*76);
            int rem = e % (24*76);
            int o   = rem / 76;
            int col = rem % 76;
            int tap = col >> 3, cc = col & 7;
            uint32_t v = 0u;
            if (o < OFFC && col < 72)
                v = f2tf32(off_w[(o*CC + c8*8 + cc)*9 + tap]);
            g_offwB[e] = v;
        }
    }
}

// ---------------------------------------------------------------------------
// K0b: NCHW -> NHWC transpose of x (fp32, exact)
// block: 32 px x 64 ch; grid 4608
// ---------------------------------------------------------------------------
__global__ __launch_bounds__(256) void nhwc_kernel(const float* __restrict__ x) {
    __shared__ float ts[64*33];
    const int tid = threadIdx.x;
    const int blk = blockIdx.x;
    const int b   = blk / (HWX/32);
    const int pt  = (blk % (HWX/32)) * 32;
    const int px5 = tid & 31, cg = tid >> 5;

    #pragma unroll
    for (int it = 0; it < 8; ++it) {
        int ch = it*8 + cg;
        ts[ch*33 + px5] = x[((size_t)(b*CC + ch))*HWX + pt + px5];
    }
    __syncthreads();
    const int px = tid >> 3;
    #pragma unroll
    for (int it = 0; it < 2; ++it) {
        int g = (tid & 7) + it*8;
        float4 v;
        v.x = ts[(4*g  )*33 + px];
        v.y = ts[(4*g+1)*33 + px];
        v.z = ts[(4*g+2)*33 + px];
        v.w = ts[(4*g+3)*33 + px];
        ((float4*)g_xT)[((size_t)b*HWX + pt + px)*16 + g] = v;
    }
}

// ---------------------------------------------------------------------------
// K1: 3x3 conv 64 -> 18 via mma.sync tf32 (R10, validated)
// ---------------------------------------------------------------------------
__global__ __launch_bounds__(256) void offset_conv_kernel(
        const float* __restrict__ x,
        const float* __restrict__ off_b) {
    __shared__ uint32_t halo[8*680];
    __shared__ uint32_t B_s[24*76];

    const int tid = threadIdx.x;
    const int wid = tid >> 5, lid = tid & 31;
    const int bx = blockIdx.x, by = blockIdx.y, b = blockIdx.z;
    const int klo = lid & 3, r = lid >> 2;

    float d0[4][3], d1[4][3], d2[4][3], d3[4][3];
    #pragma unroll
    for (int q = 0; q < 4; ++q)
        #pragma unroll
        for (int nt = 0; nt < 3; ++nt)
            { d0[q][nt]=0.f; d1[q][nt]=0.f; d2[q][nt]=0.f; d3[q][nt]=0.f; }

    const float* xb = x + (size_t)b*CC*HWX;

    #pragma unroll 1
    for (int c8 = 0; c8 < 8; ++c8) {
        __syncthreads();
        for (int t = tid; t < 5280; t += 256) {
            int ch = t / 660, rem = t % 660;
            int rr = rem / 66, q = rem % 66;
            int gy = by*8 + rr - 1, gx = bx*64 + q - 1;
            float v = 0.f;
            if (gy >= 0 && gy < HH && gx >= 0 && gx < WW)
                v = xb[(c8*8 + ch)*HWX + gy*WW + gx];
            halo[ch*680 + rr*66 + q] = f2tf32(v);
        }
        {
            const uint4* src = (const uint4*)(g_offwB + c8*24*76);
            uint4* dst = (uint4*)B_s;
            for (int t = tid; t < 456; t += 256) dst[t] = src[t];
        }
        __syncthreads();

        #pragma unroll
        for (int tap = 0; tap < 9; ++tap) {
            const int i = tap/3, j = tap%3;
            uint32_t b0[3], b1[3];
            #pragma unroll
            for (int nt = 0; nt < 3; ++nt) {
                b0[nt] = B_s[(nt*8 + r)*76 + tap*8 + klo];
                b1[nt] = B_s[(nt*8 + r)*76 + tap*8 + klo + 4];
            }
            #pragma unroll
            for (int q = 0; q < 4; ++q) {
                int a_idx = klo*680 + (wid + i)*66 + q*16 + r + j;
                uint32_t a0 = halo[a_idx];
                uint32_t a1 = halo[a_idx + 8];
                uint32_t a2 = halo[a_idx + 4*680];
                uint32_t a3 = halo[a_idx + 4*680 + 8];
                #pragma unroll
                for (int nt = 0; nt < 3; ++nt)
                    MMA_TF32(d0[q][nt], d1[q][nt], d2[q][nt], d3[q][nt],
                             a0, a1, a2, a3, b0[nt], b1[nt]);
            }
        }
    }

    const int yg = by*8 + wid;
    #pragma unroll
    for (int q = 0; q < 4; ++q) {
        int px0 = bx*64 + q*16 + r;
        #pragma unroll
        for (int nt = 0; nt < 3; ++nt) {
            int o0 = nt*8 + 2*klo, o1 = o0 + 1;
            if (o0 < OFFC) {
                float bv = off_b[o0];
                float* dst = &g_off[((size_t)(b*OFFC + o0)*HH + yg)*WW + px0];
                dst[0] = d0[q][nt] + bv;
                dst[8] = d2[q][nt] + bv;
            }
            if (o1 < OFFC) {
                float bv = off_b[o1];
                float* dst = &g_off[((size_t)(b*OFFC + o1)*HH + yg)*WW + px0];
                dst[0] = d1[q][nt] + bv;
                dst[8] = d3[q][nt] + bv;
            }
        }
    }
}

// ---------------------------------------------------------------------------
// K2: deformable conv via mma.sync tf32, software-pipelined, NHWC gather.
// block = 1 row x 64 px (M), 64 outch (N); 256 thr; grid (3, 192, 4).
// Double-buffered A/B/meta; one __syncthreads per tap.
// ---------------------------------------------------------------------------
__global__ __launch_bounds__(256, 3) void deform_bn_kernel(
        const float* __restrict__ db,
        const float* __restrict__ gma,
        const float* __restrict__ bta,
        const float* __restrict__ mean,
        const float* __restrict__ var) {
    extern __shared__ __align__(16) float smem[];
    float* sc_s = smem + SCS_OFF;
    float* sh_s = smem + SHS_OFF;
    float* A_s  = smem + A_OFF;     // [2][64][68] tf32 bits
    float* B_s  = smem + B_OFF;     // [2][64][68] tf32 bits
    float* M_s  = smem + M_OFF;     // [2][64][8] metadata

    const int tid = threadIdx.x;
    const int wid = tid >> 5, lid = tid & 31;
    const int b   = blockIdx.z;
    const int y   = blockIdx.y;
    const int x0b = blockIdx.x * 64;

    if (tid < 64) {
        float sc = gma[tid] * rsqrtf(var[tid] + 1e-5f);
        sc_s[tid] = sc;
        sh_s[tid] = (db[tid] - mean[tid])*sc + bta[tid];
    }

    const float* xb = g_xT + (size_t)b*HWX*CC;

    // ---- helper lambdas ----
    auto compute_meta = [&](int kk, int mb) {
        if (tid < 64) {
            int xx = x0b + tid;
            int i = kk/3, j = kk%3;
            float oy = g_off[((size_t)(b*OFFC + 2*kk  )*HH + y)*WW + xx];
            float ox = g_off[((size_t)(b*OFFC + 2*kk+1)*HH + y)*WW + xx];
            float py = (float)(y  + i - 1) + oy;
            float px = (float)(xx + j - 1) + ox;
            float fy = floorf(py), fx = floorf(px);
            int yq = (int)fy, xq = (int)fx;
            float wy = py - fy, wx = px - fx;
            float vy0 = ((unsigned)yq     < (unsigned)HH) ? 1.f : 0.f;
            float vy1 = ((unsigned)(yq+1) < (unsigned)HH) ? 1.f : 0.f;
            float vx0 = ((unsigned)xq     < (unsigned)WW) ? 1.f : 0.f;
            float vx1 = ((unsigned)(xq+1) < (unsigned)WW) ? 1.f : 0.f;
            float uA = (1.f - wy)*vy0, uB = wy*vy1;
            float wA = (1.f - wx)*vx0, wB = wx*vx1;
            int yb0 = min(max(yq,   0), HH-1);
            int yb1 = min(max(yq+1, 0), HH-1);
            int xc0 = min(max(xq,   0), WW-1);
            int xc1 = min(max(xq+1, 0), WW-1);
            float* mp = M_s + mb*512 + tid*8;
            mp[0] = __uint_as_float((uint32_t)((yb0*WW + xc0)*CC));
            mp[1] = __uint_as_float((uint32_t)((yb1*WW + xc0)*CC));
            mp[2] = __uint_as_float((uint32_t)((xc1 - xc0)*CC));
            mp[3] = uA; mp[4] = uB; mp[5] = wA; mp[6] = wB; mp[7] = 0.f;
        }
    };
    auto stage_B = [&](int kk, int bf) {
        const float4* src = (const float4*)(g_dwT + kk*4096);
        float* dst = B_s + bf*ABUF;
        for (int t = tid; t < 1024; t += 256) {
            int o = t >> 4, c4 = t & 15;
            ((float4*)(dst + o*68))[c4] = src[t];
        }
    };
    auto gather = [&](int abuf, int mb) {
        const int half = lid >> 4, ch4 = lid & 15;
        #pragma unroll
        for (int it = 0; it < 4; ++it) {
            int px = (wid << 3) + (it << 1) + half;
            const float* mp = M_s + mb*512 + px*8;
            float4 m0 = *(const float4*)mp;
            float4 m1 = *(const float4*)(mp + 4);
            uint32_t base0 = __float_as_uint(m0.x);
            uint32_t base1 = __float_as_uint(m0.y);
            uint32_t dx    = __float_as_uint(m0.z);
            float uA = m0.w, uB = m1.x, wA = m1.y, wB = m1.z;
            float4 cA0 = ((const float4*)(xb + base0     ))[ch4];
            float4 cA1 = ((const float4*)(xb + base0 + dx))[ch4];
            float4 cB0 = ((const float4*)(xb + base1     ))[ch4];
            float4 cB1 = ((const float4*)(xb + base1 + dx))[ch4];
            float t0x = uA*cA0.x + uB*cB0.x, t1x = uA*cA1.x + uB*cB1.x;
            float t0y = uA*cA0.y + uB*cB0.y, t1y = uA*cA1.y + uB*cB1.y;
            float t0z = uA*cA0.z + uB*cB0.z, t1z = uA*cA1.z + uB*cB1.z;
            float t0w = uA*cA0.w + uB*cB0.w, t1w = uA*cA1.w + uB*cB1.w;
            uint4 pk;
            pk.x = f2tf32(wA*t0x + wB*t1x);
            pk.y = f2tf32(wA*t0y + wB*t1y);
            pk.z = f2tf32(wA*t0z + wB*t1z);
            pk.w = f2tf32(wA*t0w + wB*t1w);
            ((uint4*)(A_s + abuf*ABUF + px*68))[ch4] = pk;
        }
    };

    // D fragments: [mt][nt][4]
    float d[2][2][4];
    #pragma unroll
    for (int mt = 0; mt < 2; ++mt)
        #pragma unroll
        for (int nt = 0; nt < 2; ++nt)
            { d[mt][nt][0]=0.f; d[mt][nt][1]=0.f; d[mt][nt][2]=0.f; d[mt][nt][3]=0.f; }

    const int mg = wid & 1, ng = wid >> 1;
    const int r4 = lid >> 2, klo = lid & 3;

    // prologue
    compute_meta(0, 0);
    __syncthreads();
    stage_B(0, 0);
    gather(0, 0);
    compute_meta(1, 1);
    __syncthreads();

    #pragma unroll 1
    for (int kk = 0; kk < 9; ++kk) {
        const int buf = kk & 1, nxt = buf ^ 1;
        if (kk < 8) {
            stage_B(kk + 1, nxt);
            if (kk < 7) compute_meta(kk + 2, buf);
            gather(nxt, nxt);
        }
        // MMA on tap kk from buf
        {
            const float* Ab = A_s + buf*ABUF;
            const float* Bb = B_s + buf*ABUF;
            #pragma unroll
            for (int k = 0; k < 8; ++k) {
                const int col = k*8 + klo;
                uint32_t a[2][4];
                #pragma unroll
                for (int mt = 0; mt < 2; ++mt) {
                    const int row = (mg*2 + mt)*16 + r4;
                    a[mt][0] = fbits(Ab[ row     *68 + col    ]);
                    a[mt][1] = fbits(Ab[(row + 8)*68 + col    ]);
                    a[mt][2] = fbits(Ab[ row     *68 + col + 4]);
                    a[mt][3] = fbits(Ab[(row + 8)*68 + col + 4]);
                }
                #pragma unroll
                for (int nt = 0; nt < 2; ++nt) {
                    const int orow = (ng*2 + nt)*8 + r4;
                    uint32_t b0 = fbits(Bb[orow*68 + col]);
                    uint32_t b1 = fbits(Bb[orow*68 + col + 4]);
                    MMA_TF32(d[0][nt][0], d[0][nt][1], d[0][nt][2], d[0][nt][3],
                             a[0][0], a[0][1], a[0][2], a[0][3], b0, b1);
                    MMA_TF32(d[1][nt][0], d[1][nt][1], d[1][nt][2], d[1][nt][3],
                             a[1][0], a[1][1], a[1][2], a[1][3], b0, b1);
                }
            }
        }
        __syncthreads();
    }

    // epilogue: BN, store, fused pool partial sums
    #pragma unroll
    for (int nt = 0; nt < 2; ++nt) {
        const int o0 = (ng*2 + nt)*8 + klo*2;
        const int o1 = o0 + 1;
        const float sc0 = sc_s[o0], sh0 = sh_s[o0];
        const float sc1 = sc_s[o1], sh1 = sh_s[o1];
        float s0 = 0.f, s1 = 0.f;
        #pragma unroll
        for (int mt = 0; mt < 2; ++mt) {
            const int p0 = (mg*2 + mt)*16 + r4, p1 = p0 + 8;
            float v00 = d[mt][nt][0]*sc0 + sh0;
            float v01 = d[mt][nt][1]*sc1 + sh1;
            float v10 = d[mt][nt][2]*sc0 + sh0;
            float v11 = d[mt][nt][3]*sc1 + sh1;
            g_h[((size_t)(b*CC + o0)*HH + y)*WW + x0b + p0] = v00;
            g_h[((size_t)(b*CC + o1)*HH + y)*WW + x0b + p0] = v01;
            g_h[((size_t)(b*CC + o0)*HH + y)*WW + x0b + p1] = v10;
            g_h[((size_t)(b*CC + o1)*HH + y)*WW + x0b + p1] = v11;
            s0 += v00 + v10;
            s1 += v01 + v11;
        }
        #pragma unroll
        for (int off = 4; off < 32; off <<= 1) {
            s0 += __shfl_xor_sync(0xffffffffu, s0, off);
            s1 += __shfl_xor_sync(0xffffffffu, s1, off);
        }
        if (r4 == 0) {
            atomicAdd(&g_pool[b*CC + o0], s0);
            atomicAdd(&g_pool[b*CC + o1], s1);
        }
    }
}

// ---------------------------------------------------------------------------
// K3: SE MLP (hid=4)
// ---------------------------------------------------------------------------
__global__ __launch_bounds__(256) void ca_kernel(
        const float* __restrict__ w1, const float* __restrict__ b1,
        const float* __restrict__ w2, const float* __restrict__ b2) {
    __shared__ float t[BB*HID];
    const int tid = threadIdx.x;
    const int b = tid >> 6, c = tid & 63;
    if (c < HID) {
        float s = b1[c];
        for (int cc = 0; cc < CC; ++cc)
            s += w1[c*CC + cc] * (g_pool[b*CC + cc] * (1.f/(float)HWX));
        t[b*HID + c] = fmaxf(s, 0.f);
    }
    __syncthreads();
    float s = b2[c];
    #pragma unroll
    for (int h = 0; h < HID; ++h) s += w2[c*HID + h] * t[b*HID + h];
    g_cw[tid] = 1.f / (1.f + expf(-s));
}

// ---------------------------------------------------------------------------
// K4: spatial attention 7x7 conv -> sigmoid -> fused final output
// ---------------------------------------------------------------------------
__global__ __launch_bounds__(256) void sa_final_kernel(
        const float* __restrict__ sa_w, const float* __restrict__ sa_b,
        float* __restrict__ out) {
    __shared__ float ws[CC*49];
    __shared__ float xs[14*70];
    __shared__ float cws[CC];
    const int tid = threadIdx.x;
    const int bx = blockIdx.x, by = blockIdx.y, b = blockIdx.z;
    const int lx = tid & 31, ly = tid >> 5;
    const int xg0 = bx*64 + lx, yg = by*8 + ly;

    for (int t = tid; t < CC*49; t += 256) ws[t] = sa_w[t];
    if (tid < CC) cws[tid] = g_cw[b*CC + tid];

    float acc0 = sa_b[0], acc1 = sa_b[0];
    const float* hb = g_h + (size_t)b*CC*HWX;

    #pragma unroll 1
    for (int c = 0; c < CC; ++c) {
        __syncthreads();
        for (int t = tid; t < 14*70; t += 256) {
            int r = t / 70, q = t % 70;
            int gy = by*8 + r - 3, gx = bx*64 + q - 3;
            float v = 0.f;
            if (gy >= 0 && gy < HH && gx >= 0 && gx < WW)
                v = hb[c*HWX + gy*WW + gx];
            xs[t] = v;
        }
        __syncthreads();
        float s0 = 0.f, s1 = 0.f;
        #pragma unroll
        for (int dy = 0; dy < 7; ++dy) {
            #pragma unroll
            for (int dx = 0; dx < 7; ++dx) {
                float w = ws[c*49 + dy*7 + dx];
                s0 += xs[(ly+dy)*70 + lx + dx     ] * w;
                s1 += xs[(ly+dy)*70 + lx + 32 + dx] * w;
            }
        }
        acc0 += s0 * cws[c];
        acc1 += s1 * cws[c];
    }
    float sw0 = 1.f / (1.f + expf(-acc0));
    float sw1 = 1.f / (1.f + expf(-acc1));

    const int base = yg*WW + xg0;
    #pragma unroll 4
    for (int c = 0; c < CC; ++c) {
        float cw = cws[c];
        float h0 = hb[c*HWX + base];
        float h1 = hb[c*HWX + base + 32];
        out[((size_t)(b*CC + c))*HWX + base     ] = h0*cw*sw0;
        out[((size_t)(b*CC + c))*HWX + base + 32] = h1*cw*sw1;
    }
}

// ---------------------------------------------------------------------------
extern "C" void kernel_launch(void* const* d_in, const int* in_sizes, int n_in,
                              void* d_out, int out_size) {
    const float* x      = (const float*)d_in[0];
    const float* off_w  = (const float*)d_in[1];
    const float* off_b  = (const float*)d_in[2];
    const float* dw     = (const float*)d_in[3];
    const float* db     = (const float*)d_in[4];
    const float* bn_g   = (const float*)d_in[5];
    const float* bn_b   = (const float*)d_in[6];
    const float* bn_m   = (const float*)d_in[7];
    const float* bn_v   = (const float*)d_in[8];
    const float* ca_w1  = (const float*)d_in[9];
    const float* ca_b1  = (const float*)d_in[10];
    const float* ca_w2  = (const float*)d_in[11];
    const float* ca_b2  = (const float*)d_in[12];
    const float* sa_w   = (const float*)d_in[13];
    const float* sa_b   = (const float*)d_in[14];
    float* out = (float*)d_out;

    cudaFuncSetAttribute(deform_bn_kernel,
                         cudaFuncAttributeMaxDynamicSharedMemorySize,
                         DEFORM_SMEM_BYTES);

    transpose_w_kernel<<<(9*CC*CC + 8*24*76 + 255)/256, 256>>>(dw, off_w);
    nhwc_kernel       <<<BB*HWX/32, 256>>>(x);
    offset_conv_kernel<<<dim3(WW/64, HH/8, BB), 256>>>(x, off_b);
    deform_bn_kernel  <<<dim3(WW/64, HH, BB), 256, DEFORM_SMEM_BYTES>>>(
                          db, bn_g, bn_b, bn_m, bn_v);
    ca_kernel         <<<1, 256>>>(ca_w1, ca_b1, ca_w2, ca_b2);
    sa_final_kernel   <<<dim3(WW/64, HH/8, BB), 256>>>(sa_w, sa_b, out);
}

// round 12
// speedup vs baseline: 2.5036x; 1.3380x over previous
#include <cuda_runtime.h>
#include <cuda_fp16.h>
#include <math.h>
#include <stdint.h>

#define BB   4
#define CC   64
#define HH   192
#define WW   192
#define HWX  (HH*WW)
#define OFFC 18
#define HID  4

__device__ __forceinline__ uint32_t f2tf32(float f) {
    uint32_t r;
    asm("cvt.rna.tf32.f32 %0, %1;" : "=r"(r) : "f"(f));
    return r;
}

// warp-level tf32 MMA (offset conv; validated R10)
#define MMA_TF32(d0,d1,d2,d3, a0,a1,a2,a3, b0,b1)                              \
    asm volatile("mma.sync.aligned.m16n8k8.row.col.f32.tf32.tf32.f32 "         \
        "{%0,%1,%2,%3}, {%4,%5,%6,%7}, {%8,%9}, {%0,%1,%2,%3};"                \
        : "+f"(d0), "+f"(d1), "+f"(d2), "+f"(d3)                               \
        : "r"(a0), "r"(a1), "r"(a2), "r"(a3), "r"(b0), "r"(b1))

// warp-level f16 MMA, fp32 accumulate: D(16x8) += A(16x16) * B(16x8)
#define MMA_F16(d0,d1,d2,d3, a0,a1,a2,a3, b0,b1)                               \
    asm volatile("mma.sync.aligned.m16n8k16.row.col.f32.f16.f16.f32 "          \
        "{%0,%1,%2,%3}, {%4,%5,%6,%7}, {%8,%9}, {%0,%1,%2,%3};"                \
        : "+f"(d0), "+f"(d1), "+f"(d2), "+f"(d3)                               \
        : "r"(a0), "r"(a1), "r"(a2), "r"(a3), "r"(b0), "r"(b1))

// scratch (device globals; allocations are forbidden)
__device__ float g_off[BB*OFFC*HH*WW];          // 10.6 MB
__device__ float g_h  [BB*CC*HH*WW];            // 37.7 MB
__device__ __align__(16) __half g_xTh[BB*HWX*CC]; // 18.9 MB NHWC fp16 x
__device__ float g_pool[BB*CC];
__device__ float g_cw  [BB*CC];
__device__ __align__(16) __half g_dwTh[9*CC*CC]; // [kk][o][c] fp16
__device__ uint32_t g_offwB[8*24*76];           // offset-conv B panels (tf32)

// ---------------------------------------------------------------------------
// K0: weight prep
// ---------------------------------------------------------------------------
__global__ __launch_bounds__(256) void transpose_w_kernel(
        const float* __restrict__ dw, const float* __restrict__ off_w) {
    int d = blockIdx.x*256 + threadIdx.x;
    if (blockIdx.x == 0) g_pool[threadIdx.x] = 0.f;
    if (d < 9*CC*CC) {
        int kk = d >> 12;
        int o  = (d >> 6) & 63;
        int c  = d & 63;
        g_dwTh[d] = __float2half_rn(dw[(o*CC + c)*9 + kk]);
    } else {
        int e = d - 9*CC*CC;
        if (e < 8*24*76) {
            int c8  = e / (24*76);
            int rem = e % (24*76);
            int o   = rem / 76;
            int col = rem % 76;
            int tap = col >> 3, cc = col & 7;
            uint32_t v = 0u;
            if (o < OFFC && col < 72)
                v = f2tf32(off_w[(o*CC + c8*8 + cc)*9 + tap]);
            g_offwB[e] = v;
        }
    }
}

// ---------------------------------------------------------------------------
// K0b: NCHW fp32 -> NHWC fp16 transpose of x
// block: 32 px x 64 ch; grid 4608
// ---------------------------------------------------------------------------
__global__ __launch_bounds__(256) void nhwc_kernel(const float* __restrict__ x) {
    __shared__ float ts[64*33];
    const int tid = threadIdx.x;
    const int blk = blockIdx.x;
    const int b   = blk / (HWX/32);
    const int pt  = (blk % (HWX/32)) * 32;
    const int px5 = tid & 31, cg = tid >> 5;

    #pragma unroll
    for (int it = 0; it < 8; ++it) {
        int ch = it*8 + cg;
        ts[ch*33 + px5] = x[((size_t)(b*CC + ch))*HWX + pt + px5];
    }
    __syncthreads();
    const int px = tid >> 3;
    const int g  = tid & 7;          // 8 channels per group
    uint4 o;
    uint32_t* ow = (uint32_t*)&o;
    #pragma unroll
    for (int p2 = 0; p2 < 4; ++p2) {
        __half2 h = __floats2half2_rn(ts[(g*8 + 2*p2)*33 + px],
                                      ts[(g*8 + 2*p2 + 1)*33 + px]);
        ow[p2] = *(uint32_t*)&h;
    }
    ((uint4*)g_xTh)[((size_t)b*HWX + pt + px)*8 + g] = o;
}

// ---------------------------------------------------------------------------
// K1: 3x3 conv 64 -> 18 via mma.sync tf32 (R10, validated)
// ---------------------------------------------------------------------------
__global__ __launch_bounds__(256) void offset_conv_kernel(
        const float* __restrict__ x,
        const float* __restrict__ off_b) {
    __shared__ uint32_t halo[8*680];
    __shared__ uint32_t B_s[24*76];

    const int tid = threadIdx.x;
    const int wid = tid >> 5, lid = tid & 31;
    const int bx = blockIdx.x, by = blockIdx.y, b = blockIdx.z;
    const int klo = lid & 3, r = lid >> 2;

    float d0[4][3], d1[4][3], d2[4][3], d3[4][3];
    #pragma unroll
    for (int q = 0; q < 4; ++q)
        #pragma unroll
        for (int nt = 0; nt < 3; ++nt)
            { d0[q][nt]=0.f; d1[q][nt]=0.f; d2[q][nt]=0.f; d3[q][nt]=0.f; }

    const float* xb = x + (size_t)b*CC*HWX;

    #pragma unroll 1
    for (int c8 = 0; c8 < 8; ++c8) {
        __syncthreads();
        for (int t = tid; t < 5280; t += 256) {
            int ch = t / 660, rem = t % 660;
            int rr = rem / 66, q = rem % 66;
            int gy = by*8 + rr - 1, gx = bx*64 + q - 1;
            float v = 0.f;
            if (gy >= 0 && gy < HH && gx >= 0 && gx < WW)
                v = xb[(c8*8 + ch)*HWX + gy*WW + gx];
            halo[ch*680 + rr*66 + q] = f2tf32(v);
        }
        {
            const uint4* src = (const uint4*)(g_offwB + c8*24*76);
            uint4* dst = (uint4*)B_s;
            for (int t = tid; t < 456; t += 256) dst[t] = src[t];
        }
        __syncthreads();

        #pragma unroll
        for (int tap = 0; tap < 9; ++tap) {
            const int i = tap/3, j = tap%3;
            uint32_t b0[3], b1[3];
            #pragma unroll
            for (int nt = 0; nt < 3; ++nt) {
                b0[nt] = B_s[(nt*8 + r)*76 + tap*8 + klo];
                b1[nt] = B_s[(nt*8 + r)*76 + tap*8 + klo + 4];
            }
            #pragma unroll
            for (int q = 0; q < 4; ++q) {
                int a_idx = klo*680 + (wid + i)*66 + q*16 + r + j;
                uint32_t a0 = halo[a_idx];
                uint32_t a1 = halo[a_idx + 8];
                uint32_t a2 = halo[a_idx + 4*680];
                uint32_t a3 = halo[a_idx + 4*680 + 8];
                #pragma unroll
                for (int nt = 0; nt < 3; ++nt)
                    MMA_TF32(d0[q][nt], d1[q][nt], d2[q][nt], d3[q][nt],
                             a0, a1, a2, a3, b0[nt], b1[nt]);
            }
        }
    }

    const int yg = by*8 + wid;
    #pragma unroll
    for (int q = 0; q < 4; ++q) {
        int px0 = bx*64 + q*16 + r;
        #pragma unroll
        for (int nt = 0; nt < 3; ++nt) {
            int o0 = nt*8 + 2*klo, o1 = o0 + 1;
            if (o0 < OFFC) {
                float bv = off_b[o0];
                float* dst = &g_off[((size_t)(b*OFFC + o0)*HH + yg)*WW + px0];
                dst[0] = d0[q][nt] + bv;
                dst[8] = d2[q][nt] + bv;
            }
            if (o1 < OFFC) {
                float bv = off_b[o1];
                float* dst = &g_off[((size_t)(b*OFFC + o1)*HH + yg)*WW + px0];
                dst[0] = d1[q][nt] + bv;
                dst[8] = d3[q][nt] + bv;
            }
        }
    }
}

// ---------------------------------------------------------------------------
// K2: deformable conv via f16 mma (fp32 accum), pipelined, fp16 NHWC gather.
// block = 1 row x 64 px (M), 64 outch (N); 256 thr; grid (3, 192, 4).
// ---------------------------------------------------------------------------
__global__ __launch_bounds__(256, 3) void deform_bn_kernel(
        const float* __restrict__ db,
        const float* __restrict__ gma,
        const float* __restrict__ bta,
        const float* __restrict__ mean,
        const float* __restrict__ var) {
    __shared__ uint32_t A_s[2][64*36];   // [buf][px][36 words] f16x2
    __shared__ uint32_t B_s[2][64*36];   // [buf][o][36 words]  f16x2
    __shared__ float    M_s[2][512];     // [buf][px][8] metadata
    __shared__ float    sc_s[64], sh_s[64];

    const int tid = threadIdx.x;
    const int wid = tid >> 5, lid = tid & 31;
    const int b   = blockIdx.z;
    const int y   = blockIdx.y;
    const int x0b = blockIdx.x * 64;

    if (tid < 64) {
        float sc = gma[tid] * rsqrtf(var[tid] + 1e-5f);
        sc_s[tid] = sc;
        sh_s[tid] = (db[tid] - mean[tid])*sc + bta[tid];
    }

    const __half* xh = g_xTh + (size_t)b*HWX*CC;

    auto compute_meta = [&](int kk, int mb) {
        if (tid < 64) {
            int xx = x0b + tid;
            int i = kk/3, j = kk%3;
            float oy = g_off[((size_t)(b*OFFC + 2*kk  )*HH + y)*WW + xx];
            float ox = g_off[((size_t)(b*OFFC + 2*kk+1)*HH + y)*WW + xx];
            float py = (float)(y  + i - 1) + oy;
            float px = (float)(xx + j - 1) + ox;
            float fy = floorf(py), fx = floorf(px);
            int yq = (int)fy, xq = (int)fx;
            float wy = py - fy, wx = px - fx;
            float vy0 = ((unsigned)yq     < (unsigned)HH) ? 1.f : 0.f;
            float vy1 = ((unsigned)(yq+1) < (unsigned)HH) ? 1.f : 0.f;
            float vx0 = ((unsigned)xq     < (unsigned)WW) ? 1.f : 0.f;
            float vx1 = ((unsigned)(xq+1) < (unsigned)WW) ? 1.f : 0.f;
            float uA = (1.f - wy)*vy0, uB = wy*vy1;
            float wA = (1.f - wx)*vx0, wB = wx*vx1;
            int yb0 = min(max(yq,   0), HH-1);
            int yb1 = min(max(yq+1, 0), HH-1);
            int xc0 = min(max(xq,   0), WW-1);
            int xc1 = min(max(xq+1, 0), WW-1);
            float* mp = M_s[mb] + tid*8;
            mp[0] = __uint_as_float((uint32_t)((yb0*WW + xc0)*CC));
            mp[1] = __uint_as_float((uint32_t)((yb1*WW + xc0)*CC));
            mp[2] = __uint_as_float((uint32_t)((xc1 - xc0)*CC));
            mp[3] = uA; mp[4] = uB; mp[5] = wA; mp[6] = wB; mp[7] = 0.f;
        }
    };
    auto stage_B = [&](int kk, int bf) {
        const uint4* src = (const uint4*)(g_dwTh + kk*4096);
        #pragma unroll 2
        for (int t = tid; t < 512; t += 256) {
            int o = t >> 3, w4 = t & 7;
            ((uint4*)(&B_s[bf][o*36]))[w4] = src[o*8 + w4];
        }
    };
    auto gather = [&](int abuf, int mb) {
        const int c8 = lid & 7, pq = lid >> 3;
        #pragma unroll
        for (int it = 0; it < 2; ++it) {
            int px = (wid << 3) + (it << 2) + pq;
            const float* mp = M_s[mb] + px*8;
            float4 m0 = *(const float4*)mp;
            float4 m1 = *(const float4*)(mp + 4);
            uint32_t base0 = __float_as_uint(m0.x);
            uint32_t base1 = __float_as_uint(m0.y);
            uint32_t dx    = __float_as_uint(m0.z);
            float uA = m0.w, uB = m1.x, wA = m1.y, wB = m1.z;
            uint4 cA0 = ((const uint4*)(xh + base0     ))[c8];
            uint4 cA1 = ((const uint4*)(xh + base0 + dx))[c8];
            uint4 cB0 = ((const uint4*)(xh + base1     ))[c8];
            uint4 cB1 = ((const uint4*)(xh + base1 + dx))[c8];
            const uint32_t* wa0 = (const uint32_t*)&cA0;
            const uint32_t* wa1 = (const uint32_t*)&cA1;
            const uint32_t* wb0 = (const uint32_t*)&cB0;
            const uint32_t* wb1 = (const uint32_t*)&cB1;
            uint4 out;
            uint32_t* ow = (uint32_t*)&out;
            #pragma unroll
            for (int p = 0; p < 4; ++p) {
                float2 fa0 = __half22float2(*(const __half2*)&wa0[p]);
                float2 fa1 = __half22float2(*(const __half2*)&wa1[p]);
                float2 fb0 = __half22float2(*(const __half2*)&wb0[p]);
                float2 fb1 = __half22float2(*(const __half2*)&wb1[p]);
                float t0x = uA*fa0.x + uB*fb0.x, t1x = uA*fa1.x + uB*fb1.x;
                float t0y = uA*fa0.y + uB*fb0.y, t1y = uA*fa1.y + uB*fb1.y;
                __half2 h = __floats2half2_rn(wA*t0x + wB*t1x, wA*t0y + wB*t1y);
                ow[p] = *(const uint32_t*)&h;
            }
            ((uint4*)(&A_s[abuf][px*36]))[c8] = out;
        }
    };

    float d[2][2][4];
    #pragma unroll
    for (int mt = 0; mt < 2; ++mt)
        #pragma unroll
        for (int nt = 0; nt < 2; ++nt)
            { d[mt][nt][0]=0.f; d[mt][nt][1]=0.f; d[mt][nt][2]=0.f; d[mt][nt][3]=0.f; }

    const int mg = wid & 1, ng = wid >> 1;
    const int r4 = lid >> 2, klo = lid & 3;

    // prologue
    compute_meta(0, 0);
    __syncthreads();
    stage_B(0, 0);
    gather(0, 0);
    compute_meta(1, 1);
    __syncthreads();

    #pragma unroll 1
    for (int kk = 0; kk < 9; ++kk) {
        const int buf = kk & 1, nxt = buf ^ 1;
        if (kk < 8) {
            stage_B(kk + 1, nxt);
            if (kk < 7) compute_meta(kk + 2, buf);
            gather(nxt, nxt);
        }
        {
            const uint32_t* Ab = A_s[buf];
            const uint32_t* Bb = B_s[buf];
            #pragma unroll
            for (int s = 0; s < 4; ++s) {
                const int kw = s*8 + klo;
                uint32_t a[2][4];
                #pragma unroll
                for (int mt = 0; mt < 2; ++mt) {
                    const int row = (mg*2 + mt)*16 + r4;
                    a[mt][0] = Ab[ row     *36 + kw    ];
                    a[mt][1] = Ab[(row + 8)*36 + kw    ];
                    a[mt][2] = Ab[ row     *36 + kw + 4];
                    a[mt][3] = Ab[(row + 8)*36 + kw + 4];
                }
                #pragma unroll
                for (int nt = 0; nt < 2; ++nt) {
                    const int orow = (ng*2 + nt)*8 + r4;
                    uint32_t b0 = Bb[orow*36 + kw];
                    uint32_t b1 = Bb[orow*36 + kw + 4];
                    MMA_F16(d[0][nt][0], d[0][nt][1], d[0][nt][2], d[0][nt][3],
                            a[0][0], a[0][1], a[0][2], a[0][3], b0, b1);
                    MMA_F16(d[1][nt][0], d[1][nt][1], d[1][nt][2], d[1][nt][3],
                            a[1][0], a[1][1], a[1][2], a[1][3], b0, b1);
                }
            }
        }
        __syncthreads();
    }

    // epilogue: BN, store, fused pool partial sums (D layout == m16n8, as R9-11)
    #pragma unroll
    for (int nt = 0; nt < 2; ++nt) {
        const int o0 = (ng*2 + nt)*8 + klo*2;
        const int o1 = o0 + 1;
        const float sc0 = sc_s[o0], sh0 = sh_s[o0];
        const float sc1 = sc_s[o1], sh1 = sh_s[o1];
        float s0 = 0.f, s1 = 0.f;
        #pragma unroll
        for (int mt = 0; mt < 2; ++mt) {
            const int p0 = (mg*2 + mt)*16 + r4, p1 = p0 + 8;
            float v00 = d[mt][nt][0]*sc0 + sh0;
            float v01 = d[mt][nt][1]*sc1 + sh1;
            float v10 = d[mt][nt][2]*sc0 + sh0;
            float v11 = d[mt][nt][3]*sc1 + sh1;
            g_h[((size_t)(b*CC + o0)*HH + y)*WW + x0b + p0] = v00;
            g_h[((size_t)(b*CC + o1)*HH + y)*WW + x0b + p0] = v01;
            g_h[((size_t)(b*CC + o0)*HH + y)*WW + x0b + p1] = v10;
            g_h[((size_t)(b*CC + o1)*HH + y)*WW + x0b + p1] = v11;
            s0 += v00 + v10;
            s1 += v01 + v11;
        }
        #pragma unroll
        for (int off = 4; off < 32; off <<= 1) {
            s0 += __shfl_xor_sync(0xffffffffu, s0, off);
            s1 += __shfl_xor_sync(0xffffffffu, s1, off);
        }
        if (r4 == 0) {
            atomicAdd(&g_pool[b*CC + o0], s0);
            atomicAdd(&g_pool[b*CC + o1], s1);
        }
    }
}

// ---------------------------------------------------------------------------
// K3: SE MLP (hid=4)
// ---------------------------------------------------------------------------
__global__ __launch_bounds__(256) void ca_kernel(
        const float* __restrict__ w1, const float* __restrict__ b1,
        const float* __restrict__ w2, const float* __restrict__ b2) {
    __shared__ float t[BB*HID];
    const int tid = threadIdx.x;
    const int b = tid >> 6, c = tid & 63;
    if (c < HID) {
        float s = b1[c];
        for (int cc = 0; cc < CC; ++cc)
            s += w1[c*CC + cc] * (g_pool[b*CC + cc] * (1.f/(float)HWX));
        t[b*HID + c] = fmaxf(s, 0.f);
    }
    __syncthreads();
    float s = b2[c];
    #pragma unroll
    for (int h = 0; h < HID; ++h) s += w2[c*HID + h] * t[b*HID + h];
    g_cw[tid] = 1.f / (1.f + expf(-s));
}

// ---------------------------------------------------------------------------
// K4: spatial attention 7x7 conv -> sigmoid -> fused final output
// ---------------------------------------------------------------------------
__global__ __launch_bounds__(256) void sa_final_kernel(
        const float* __restrict__ sa_w, const float* __restrict__ sa_b,
        float* __restrict__ out) {
    __shared__ float ws[CC*49];
    __shared__ float xs[14*70];
    __shared__ float cws[CC];
    const int tid = threadIdx.x;
    const int bx = blockIdx.x, by = blockIdx.y, b = blockIdx.z;
    const int lx = tid & 31, ly = tid >> 5;
    const int xg0 = bx*64 + lx, yg = by*8 + ly;

    for (int t = tid; t < CC*49; t += 256) ws[t] = sa_w[t];
    if (tid < CC) cws[tid] = g_cw[b*CC + tid];

    float acc0 = sa_b[0], acc1 = sa_b[0];
    const float* hb = g_h + (size_t)b*CC*HWX;

    #pragma unroll 1
    for (int c = 0; c < CC; ++c) {
        __syncthreads();
        for (int t = tid; t < 14*70; t += 256) {
            int r = t / 70, q = t % 70;
            int gy = by*8 + r - 3, gx = bx*64 + q - 3;
            float v = 0.f;
            if (gy >= 0 && gy < HH && gx >= 0 && gx < WW)
                v = hb[c*HWX + gy*WW + gx];
            xs[t] = v;
        }
        __syncthreads();
        float s0 = 0.f, s1 = 0.f;
        #pragma unroll
        for (int dy = 0; dy < 7; ++dy) {
            #pragma unroll
            for (int dx = 0; dx < 7; ++dx) {
                float w = ws[c*49 + dy*7 + dx];
                s0 += xs[(ly+dy)*70 + lx + dx     ] * w;
                s1 += xs[(ly+dy)*70 + lx + 32 + dx] * w;
            }
        }
        acc0 += s0 * cws[c];
        acc1 += s1 * cws[c];
    }
    float sw0 = 1.f / (1.f + expf(-acc0));
    float sw1 = 1.f / (1.f + expf(-acc1));

    const int base = yg*WW + xg0;
    #pragma unroll 4
    for (int c = 0; c < CC; ++c) {
        float cw = cws[c];
        float h0 = hb[c*HWX + base];
        float h1 = hb[c*HWX + base + 32];
        out[((size_t)(b*CC + c))*HWX + base     ] = h0*cw*sw0;
        out[((size_t)(b*CC + c))*HWX + base + 32] = h1*cw*sw1;
    }
}

// ---------------------------------------------------------------------------
extern "C" void kernel_launch(void* const* d_in, const int* in_sizes, int n_in,
                              void* d_out, int out_size) {
    const float* x      = (const float*)d_in[0];
    const float* off_w  = (const float*)d_in[1];
    const float* off_b  = (const float*)d_in[2];
    const float* dw     = (const float*)d_in[3];
    const float* db     = (const float*)d_in[4];
    const float* bn_g   = (const float*)d_in[5];
    const float* bn_b   = (const float*)d_in[6];
    const float* bn_m   = (const float*)d_in[7];
    const float* bn_v   = (const float*)d_in[8];
    const float* ca_w1  = (const float*)d_in[9];
    const float* ca_b1  = (const float*)d_in[10];
    const float* ca_w2  = (const float*)d_in[11];
    const float* ca_b2  = (const float*)d_in[12];
    const float* sa_w   = (const float*)d_in[13];
    const float* sa_b   = (const float*)d_in[14];
    float* out = (float*)d_out;

    transpose_w_kernel<<<(9*CC*CC + 8*24*76 + 255)/256, 256>>>(dw, off_w);
    nhwc_kernel       <<<BB*HWX/32, 256>>>(x);
    offset_conv_kernel<<<dim3(WW/64, HH/8, BB), 256>>>(x, off_b);
    deform_bn_kernel  <<<dim3(WW/64, HH, BB), 256>>>(db, bn_g, bn_b, bn_m, bn_v);
    ca_kernel         <<<1, 256>>>(ca_w1, ca_b1, ca_w2, ca_b2);
    sa_final_kernel   <<<dim3(WW/64, HH/8, BB), 256>>>(sa_w, sa_b, out);
}

// round 13
// speedup vs baseline: 3.3384x; 1.3334x over previous
#include <cuda_runtime.h>
#include <cuda_fp16.h>
#include <math.h>
#include <stdint.h>

#define BB   4
#define CC   64
#define HH   192
#define WW   192
#define HWX  (HH*WW)
#define OFFC 18
#define HID  4

__device__ __forceinline__ uint32_t f2tf32(float f) {
    uint32_t r;
    asm("cvt.rna.tf32.f32 %0, %1;" : "=r"(r) : "f"(f));
    return r;
}

// warp-level tf32 MMA (offset conv; validated R10)
#define MMA_TF32(d0,d1,d2,d3, a0,a1,a2,a3, b0,b1)                              \
    asm volatile("mma.sync.aligned.m16n8k8.row.col.f32.tf32.tf32.f32 "         \
        "{%0,%1,%2,%3}, {%4,%5,%6,%7}, {%8,%9}, {%0,%1,%2,%3};"                \
        : "+f"(d0), "+f"(d1), "+f"(d2), "+f"(d3)                               \
        : "r"(a0), "r"(a1), "r"(a2), "r"(a3), "r"(b0), "r"(b1))

// warp-level f16 MMA, fp32 accumulate: D(16x8) += A(16x16) * B(16x8)
#define MMA_F16(d0,d1,d2,d3, a0,a1,a2,a3, b0,b1)                               \
    asm volatile("mma.sync.aligned.m16n8k16.row.col.f32.f16.f16.f32 "          \
        "{%0,%1,%2,%3}, {%4,%5,%6,%7}, {%8,%9}, {%0,%1,%2,%3};"                \
        : "+f"(d0), "+f"(d1), "+f"(d2), "+f"(d3)                               \
        : "r"(a0), "r"(a1), "r"(a2), "r"(a3), "r"(b0), "r"(b1))

// scratch (device globals; allocations are forbidden)
__device__ float g_off[BB*OFFC*HH*WW];            // 10.6 MB
__device__ float g_h  [BB*CC*HH*WW];              // 37.7 MB
__device__ __align__(16) __half g_xTh[BB*HWX*CC]; // 18.9 MB NHWC fp16 x
__device__ float g_Y  [BB*49*HWX];                // 28.9 MB tap maps
__device__ float g_pool[BB*CC];
__device__ float g_cw  [BB*CC];
__device__ __align__(16) __half g_dwTh[9*CC*CC];  // [kk][o][c] fp16
__device__ uint32_t g_offwB[8*24*76];             // offset-conv B panels (tf32)

// ---------------------------------------------------------------------------
// K0: weight prep
// ---------------------------------------------------------------------------
__global__ __launch_bounds__(256) void transpose_w_kernel(
        const float* __restrict__ dw, const float* __restrict__ off_w) {
    int d = blockIdx.x*256 + threadIdx.x;
    if (blockIdx.x == 0) g_pool[threadIdx.x] = 0.f;
    if (d < 9*CC*CC) {
        int kk = d >> 12;
        int o  = (d >> 6) & 63;
        int c  = d & 63;
        g_dwTh[d] = __float2half_rn(dw[(o*CC + c)*9 + kk]);
    } else {
        int e = d - 9*CC*CC;
        if (e < 8*24*76) {
            int c8  = e / (24*76);
            int rem = e % (24*76);
            int o   = rem / 76;
            int col = rem % 76;
            int tap = col >> 3, cc = col & 7;
            uint32_t v = 0u;
            if (o < OFFC && col < 72)
                v = f2tf32(off_w[(o*CC + c8*8 + cc)*9 + tap]);
            g_offwB[e] = v;
        }
    }
}

// ---------------------------------------------------------------------------
// K0b: NCHW fp32 -> NHWC fp16 transpose of x
// ---------------------------------------------------------------------------
__global__ __launch_bounds__(256) void nhwc_kernel(const float* __restrict__ x) {
    __shared__ float ts[64*33];
    const int tid = threadIdx.x;
    const int blk = blockIdx.x;
    const int b   = blk / (HWX/32);
    const int pt  = (blk % (HWX/32)) * 32;
    const int px5 = tid & 31, cg = tid >> 5;

    #pragma unroll
    for (int it = 0; it < 8; ++it) {
        int ch = it*8 + cg;
        ts[ch*33 + px5] = x[((size_t)(b*CC + ch))*HWX + pt + px5];
    }
    __syncthreads();
    const int px = tid >> 3;
    const int g  = tid & 7;
    uint4 o;
    uint32_t* ow = (uint32_t*)&o;
    #pragma unroll
    for (int p2 = 0; p2 < 4; ++p2) {
        __half2 h = __floats2half2_rn(ts[(g*8 + 2*p2)*33 + px],
                                      ts[(g*8 + 2*p2 + 1)*33 + px]);
        ow[p2] = *(uint32_t*)&h;
    }
    ((uint4*)g_xTh)[((size_t)b*HWX + pt + px)*8 + g] = o;
}

// ---------------------------------------------------------------------------
// K1: 3x3 conv 64 -> 18 via mma.sync tf32 (R10, validated)
// ---------------------------------------------------------------------------
__global__ __launch_bounds__(256) void offset_conv_kernel(
        const float* __restrict__ x,
        const float* __restrict__ off_b) {
    __shared__ uint32_t halo[8*680];
    __shared__ uint32_t B_s[24*76];

    const int tid = threadIdx.x;
    const int wid = tid >> 5, lid = tid & 31;
    const int bx = blockIdx.x, by = blockIdx.y, b = blockIdx.z;
    const int klo = lid & 3, r = lid >> 2;

    float d0[4][3], d1[4][3], d2[4][3], d3[4][3];
    #pragma unroll
    for (int q = 0; q < 4; ++q)
        #pragma unroll
        for (int nt = 0; nt < 3; ++nt)
            { d0[q][nt]=0.f; d1[q][nt]=0.f; d2[q][nt]=0.f; d3[q][nt]=0.f; }

    const float* xb = x + (size_t)b*CC*HWX;

    #pragma unroll 1
    for (int c8 = 0; c8 < 8; ++c8) {
        __syncthreads();
        for (int t = tid; t < 5280; t += 256) {
            int ch = t / 660, rem = t % 660;
            int rr = rem / 66, q = rem % 66;
            int gy = by*8 + rr - 1, gx = bx*64 + q - 1;
            float v = 0.f;
            if (gy >= 0 && gy < HH && gx >= 0 && gx < WW)
                v = xb[(c8*8 + ch)*HWX + gy*WW + gx];
            halo[ch*680 + rr*66 + q] = f2tf32(v);
        }
        {
            const uint4* src = (const uint4*)(g_offwB + c8*24*76);
            uint4* dst = (uint4*)B_s;
            for (int t = tid; t < 456; t += 256) dst[t] = src[t];
        }
        __syncthreads();

        #pragma unroll
        for (int tap = 0; tap < 9; ++tap) {
            const int i = tap/3, j = tap%3;
            uint32_t b0[3], b1[3];
            #pragma unroll
            for (int nt = 0; nt < 3; ++nt) {
                b0[nt] = B_s[(nt*8 + r)*76 + tap*8 + klo];
                b1[nt] = B_s[(nt*8 + r)*76 + tap*8 + klo + 4];
            }
            #pragma unroll
            for (int q = 0; q < 4; ++q) {
                int a_idx = klo*680 + (wid + i)*66 + q*16 + r + j;
                uint32_t a0 = halo[a_idx];
                uint32_t a1 = halo[a_idx + 8];
                uint32_t a2 = halo[a_idx + 4*680];
                uint32_t a3 = halo[a_idx + 4*680 + 8];
                #pragma unroll
                for (int nt = 0; nt < 3; ++nt)
                    MMA_TF32(d0[q][nt], d1[q][nt], d2[q][nt], d3[q][nt],
                             a0, a1, a2, a3, b0[nt], b1[nt]);
            }
        }
    }

    const int yg = by*8 + wid;
    #pragma unroll
    for (int q = 0; q < 4; ++q) {
        int px0 = bx*64 + q*16 + r;
        #pragma unroll
        for (int nt = 0; nt < 3; ++nt) {
            int o0 = nt*8 + 2*klo, o1 = o0 + 1;
            if (o0 < OFFC) {
                float bv = off_b[o0];
                float* dst = &g_off[((size_t)(b*OFFC + o0)*HH + yg)*WW + px0];
                dst[0] = d0[q][nt] + bv;
                dst[8] = d2[q][nt] + bv;
            }
            if (o1 < OFFC) {
                float bv = off_b[o1];
                float* dst = &g_off[((size_t)(b*OFFC + o1)*HH + yg)*WW + px0];
                dst[0] = d1[q][nt] + bv;
                dst[8] = d3[q][nt] + bv;
            }
        }
    }
}

// ---------------------------------------------------------------------------
// K2: deformable conv via f16 mma (fp32 accum), pipelined (R12, validated)
// ---------------------------------------------------------------------------
__global__ __launch_bounds__(256, 3) void deform_bn_kernel(
        const float* __restrict__ db,
        const float* __restrict__ gma,
        const float* __restrict__ bta,
        const float* __restrict__ mean,
        const float* __restrict__ var) {
    __shared__ uint32_t A_s[2][64*36];
    __shared__ uint32_t B_s[2][64*36];
    __shared__ float    M_s[2][512];
    __shared__ float    sc_s[64], sh_s[64];

    const int tid = threadIdx.x;
    const int wid = tid >> 5, lid = tid & 31;
    const int b   = blockIdx.z;
    const int y   = blockIdx.y;
    const int x0b = blockIdx.x * 64;

    if (tid < 64) {
        float sc = gma[tid] * rsqrtf(var[tid] + 1e-5f);
        sc_s[tid] = sc;
        sh_s[tid] = (db[tid] - mean[tid])*sc + bta[tid];
    }

    const __half* xh = g_xTh + (size_t)b*HWX*CC;

    auto compute_meta = [&](int kk, int mb) {
        if (tid < 64) {
            int xx = x0b + tid;
            int i = kk/3, j = kk%3;
            float oy = g_off[((size_t)(b*OFFC + 2*kk  )*HH + y)*WW + xx];
            float ox = g_off[((size_t)(b*OFFC + 2*kk+1)*HH + y)*WW + xx];
            float py = (float)(y  + i - 1) + oy;
            float px = (float)(xx + j - 1) + ox;
            float fy = floorf(py), fx = floorf(px);
            int yq = (int)fy, xq = (int)fx;
            float wy = py - fy, wx = px - fx;
            float vy0 = ((unsigned)yq     < (unsigned)HH) ? 1.f : 0.f;
            float vy1 = ((unsigned)(yq+1) < (unsigned)HH) ? 1.f : 0.f;
            float vx0 = ((unsigned)xq     < (unsigned)WW) ? 1.f : 0.f;
            float vx1 = ((unsigned)(xq+1) < (unsigned)WW) ? 1.f : 0.f;
            float uA = (1.f - wy)*vy0, uB = wy*vy1;
            float wA = (1.f - wx)*vx0, wB = wx*vx1;
            int yb0 = min(max(yq,   0), HH-1);
            int yb1 = min(max(yq+1, 0), HH-1);
            int xc0 = min(max(xq,   0), WW-1);
            int xc1 = min(max(xq+1, 0), WW-1);
            float* mp = M_s[mb] + tid*8;
            mp[0] = __uint_as_float((uint32_t)((yb0*WW + xc0)*CC));
            mp[1] = __uint_as_float((uint32_t)((yb1*WW + xc0)*CC));
            mp[2] = __uint_as_float((uint32_t)((xc1 - xc0)*CC));
            mp[3] = uA; mp[4] = uB; mp[5] = wA; mp[6] = wB; mp[7] = 0.f;
        }
    };
    auto stage_B = [&](int kk, int bf) {
        const uint4* src = (const uint4*)(g_dwTh + kk*4096);
        #pragma unroll 2
        for (int t = tid; t < 512; t += 256) {
            int o = t >> 3, w4 = t & 7;
            ((uint4*)(&B_s[bf][o*36]))[w4] = src[o*8 + w4];
        }
    };
    auto gather = [&](int abuf, int mb) {
        const int c8 = lid & 7, pq = lid >> 3;
        #pragma unroll
        for (int it = 0; it < 2; ++it) {
            int px = (wid << 3) + (it << 2) + pq;
            const float* mp = M_s[mb] + px*8;
            float4 m0 = *(const float4*)mp;
            float4 m1 = *(const float4*)(mp + 4);
            uint32_t base0 = __float_as_uint(m0.x);
            uint32_t base1 = __float_as_uint(m0.y);
            uint32_t dx    = __float_as_uint(m0.z);
            float uA = m0.w, uB = m1.x, wA = m1.y, wB = m1.z;
            uint4 cA0 = ((const uint4*)(xh + base0     ))[c8];
            uint4 cA1 = ((const uint4*)(xh + base0 + dx))[c8];
            uint4 cB0 = ((const uint4*)(xh + base1     ))[c8];
            uint4 cB1 = ((const uint4*)(xh + base1 + dx))[c8];
            const uint32_t* wa0 = (const uint32_t*)&cA0;
            const uint32_t* wa1 = (const uint32_t*)&cA1;
            const uint32_t* wb0 = (const uint32_t*)&cB0;
            const uint32_t* wb1 = (const uint32_t*)&cB1;
            uint4 out;
            uint32_t* ow = (uint32_t*)&out;
            #pragma unroll
            for (int p = 0; p < 4; ++p) {
                float2 fa0 = __half22float2(*(const __half2*)&wa0[p]);
                float2 fa1 = __half22float2(*(const __half2*)&wa1[p]);
                float2 fb0 = __half22float2(*(const __half2*)&wb0[p]);
                float2 fb1 = __half22float2(*(const __half2*)&wb1[p]);
                float t0x = uA*fa0.x + uB*fb0.x, t1x = uA*fa1.x + uB*fb1.x;
                float t0y = uA*fa0.y + uB*fb0.y, t1y = uA*fa1.y + uB*fb1.y;
                __half2 h = __floats2half2_rn(wA*t0x + wB*t1x, wA*t0y + wB*t1y);
                ow[p] = *(const uint32_t*)&h;
            }
            ((uint4*)(&A_s[abuf][px*36]))[c8] = out;
        }
    };

    float d[2][2][4];
    #pragma unroll
    for (int mt = 0; mt < 2; ++mt)
        #pragma unroll
        for (int nt = 0; nt < 2; ++nt)
            { d[mt][nt][0]=0.f; d[mt][nt][1]=0.f; d[mt][nt][2]=0.f; d[mt][nt][3]=0.f; }

    const int mg = wid & 1, ng = wid >> 1;
    const int r4 = lid >> 2, klo = lid & 3;

    compute_meta(0, 0);
    __syncthreads();
    stage_B(0, 0);
    gather(0, 0);
    compute_meta(1, 1);
    __syncthreads();

    #pragma unroll 1
    for (int kk = 0; kk < 9; ++kk) {
        const int buf = kk & 1, nxt = buf ^ 1;
        if (kk < 8) {
            stage_B(kk + 1, nxt);
            if (kk < 7) compute_meta(kk + 2, buf);
            gather(nxt, nxt);
        }
        {
            const uint32_t* Ab = A_s[buf];
            const uint32_t* Bb = B_s[buf];
            #pragma unroll
            for (int s = 0; s < 4; ++s) {
                const int kw = s*8 + klo;
                uint32_t a[2][4];
                #pragma unroll
                for (int mt = 0; mt < 2; ++mt) {
                    const int row = (mg*2 + mt)*16 + r4;
                    a[mt][0] = Ab[ row     *36 + kw    ];
                    a[mt][1] = Ab[(row + 8)*36 + kw    ];
                    a[mt][2] = Ab[ row     *36 + kw + 4];
                    a[mt][3] = Ab[(row + 8)*36 + kw + 4];
                }
                #pragma unroll
                for (int nt = 0; nt < 2; ++nt) {
                    const int orow = (ng*2 + nt)*8 + r4;
                    uint32_t b0 = Bb[orow*36 + kw];
                    uint32_t b1 = Bb[orow*36 + kw + 4];
                    MMA_F16(d[0][nt][0], d[0][nt][1], d[0][nt][2], d[0][nt][3],
                            a[0][0], a[0][1], a[0][2], a[0][3], b0, b1);
                    MMA_F16(d[1][nt][0], d[1][nt][1], d[1][nt][2], d[1][nt][3],
                            a[1][0], a[1][1], a[1][2], a[1][3], b0, b1);
                }
            }
        }
        __syncthreads();
    }

    #pragma unroll
    for (int nt = 0; nt < 2; ++nt) {
        const int o0 = (ng*2 + nt)*8 + klo*2;
        const int o1 = o0 + 1;
        const float sc0 = sc_s[o0], sh0 = sh_s[o0];
        const float sc1 = sc_s[o1], sh1 = sh_s[o1];
        float s0 = 0.f, s1 = 0.f;
        #pragma unroll
        for (int mt = 0; mt < 2; ++mt) {
            const int p0 = (mg*2 + mt)*16 + r4, p1 = p0 + 8;
            float v00 = d[mt][nt][0]*sc0 + sh0;
            float v01 = d[mt][nt][1]*sc1 + sh1;
            float v10 = d[mt][nt][2]*sc0 + sh0;
            float v11 = d[mt][nt][3]*sc1 + sh1;
            g_h[((size_t)(b*CC + o0)*HH + y)*WW + x0b + p0] = v00;
            g_h[((size_t)(b*CC + o1)*HH + y)*WW + x0b + p0] = v01;
            g_h[((size_t)(b*CC + o0)*HH + y)*WW + x0b + p1] = v10;
            g_h[((size_t)(b*CC + o1)*HH + y)*WW + x0b + p1] = v11;
            s0 += v00 + v10;
            s1 += v01 + v11;
        }
        #pragma unroll
        for (int off = 4; off < 32; off <<= 1) {
            s0 += __shfl_xor_sync(0xffffffffu, s0, off);
            s1 += __shfl_xor_sync(0xffffffffu, s1, off);
        }
        if (r4 == 0) {
            atomicAdd(&g_pool[b*CC + o0], s0);
            atomicAdd(&g_pool[b*CC + o1], s1);
        }
    }
}

// ---------------------------------------------------------------------------
// K3: SE MLP (hid=4)
// ---------------------------------------------------------------------------
__global__ __launch_bounds__(256) void ca_kernel(
        const float* __restrict__ w1, const float* __restrict__ b1,
        const float* __restrict__ w2, const float* __restrict__ b2) {
    __shared__ float t[BB*HID];
    const int tid = threadIdx.x;
    const int b = tid >> 6, c = tid & 63;
    if (c < HID) {
        float s = b1[c];
        for (int cc = 0; cc < CC; ++cc)
            s += w1[c*CC + cc] * (g_pool[b*CC + cc] * (1.f/(float)HWX));
        t[b*HID + c] = fmaxf(s, 0.f);
    }
    __syncthreads();
    float s = b2[c];
    #pragma unroll
    for (int h = 0; h < HID; ++h) s += w2[c*HID + h] * t[b*HID + h];
    g_cw[tid] = 1.f / (1.f + expf(-s));
}

// ---------------------------------------------------------------------------
// K4: Y GEMM: Y[p, tap] = sum_c (sa_w[c,tap]*cw[c]) * h[c,p]   (pointwise, f16 MMA)
// block = 64 px (M), 49->56 taps (N); 256 thr; grid (HWX/64, BB)
// ---------------------------------------------------------------------------
__global__ __launch_bounds__(256) void y_gemm_kernel(
        const float* __restrict__ sa_w) {
    __shared__ uint32_t A_s[64*36];   // [px][36 words] h f16x2
    __shared__ uint32_t B_s[56*36];   // [tap][36 words] w*cw f16x2
    __shared__ float ts[64*33];

    const int tid = threadIdx.x;
    const int wid = tid >> 5, lid = tid & 31;
    const int b   = blockIdx.y;
    const int p0b = blockIdx.x * 64;

    // stage B: B[tap][c] = sa_w[c*49+tap] * cw[b,c]  (fp16)
    for (int e = tid; e < 56*32; e += 256) {
        int tap = e >> 5, c2 = e & 31;
        __half2 v = __half2half2(__float2half(0.f));
        if (tap < 49) {
            float w0 = sa_w[(2*c2  )*49 + tap] * g_cw[b*CC + 2*c2];
            float w1 = sa_w[(2*c2+1)*49 + tap] * g_cw[b*CC + 2*c2 + 1];
            v = __floats2half2_rn(w0, w1);
        }
        B_s[tap*36 + c2] = *(const uint32_t*)&v;
    }

    // stage A: transpose h (NCHW fp32) -> [px][ch] fp16, two 32-px passes
    const int px5 = tid & 31, cg = tid >> 5;
    #pragma unroll
    for (int sub = 0; sub < 2; ++sub) {
        __syncthreads();
        #pragma unroll
        for (int it = 0; it < 8; ++it) {
            int ch = it*8 + cg;
            ts[ch*33 + px5] = g_h[((size_t)(b*CC + ch))*HWX + p0b + sub*32 + px5];
        }
        __syncthreads();
        const int c2 = tid & 31;
        #pragma unroll
        for (int it = 0; it < 4; ++it) {
            int pl = it*8 + (tid >> 5);
            __half2 h = __floats2half2_rn(ts[(2*c2)*33 + pl], ts[(2*c2+1)*33 + pl]);
            A_s[(sub*32 + pl)*36 + c2] = *(const uint32_t*)&h;
        }
    }
    __syncthreads();

    // MMA: warp = (mt, ng): mt = wid&3 (16 px), ng = wid>>2 (n-tiles 0-3 / 4-6)
    const int mt = wid & 3, ng = wid >> 2;
    const int r4 = lid >> 2, klo = lid & 3;
    const int nt0 = ng*4, ntn = ng ? 3 : 4;

    float d0[4], d1[4], d2[4], d3[4];
    #pragma unroll
    for (int i = 0; i < 4; ++i) { d0[i]=0.f; d1[i]=0.f; d2[i]=0.f; d3[i]=0.f; }

    #pragma unroll
    for (int s = 0; s < 4; ++s) {
        const int kw = s*8 + klo;
        const int row = mt*16 + r4;
        uint32_t a0 = A_s[ row     *36 + kw    ];
        uint32_t a1 = A_s[(row + 8)*36 + kw    ];
        uint32_t a2 = A_s[ row     *36 + kw + 4];
        uint32_t a3 = A_s[(row + 8)*36 + kw + 4];
        #pragma unroll
        for (int ni = 0; ni < 4; ++ni) {
            if (ni < ntn) {
                const int orow = (nt0 + ni)*8 + r4;
                uint32_t b0 = B_s[orow*36 + kw];
                uint32_t b1 = B_s[orow*36 + kw + 4];
                MMA_F16(d0[ni], d1[ni], d2[ni], d3[ni], a0, a1, a2, a3, b0, b1);
            }
        }
    }

    // write Y planes: Y[(b*49+tap)*HWX + p]
    const int pA = p0b + mt*16 + r4;
    const int pB = pA + 8;
    #pragma unroll
    for (int ni = 0; ni < 4; ++ni) {
        if (ni < ntn) {
            int t0 = (nt0 + ni)*8 + klo*2;
            int t1 = t0 + 1;
            if (t0 < 49) {
                g_Y[((size_t)(b*49 + t0))*HWX + pA] = d0[ni];
                g_Y[((size_t)(b*49 + t0))*HWX + pB] = d2[ni];
            }
            if (t1 < 49) {
                g_Y[((size_t)(b*49 + t1))*HWX + pA] = d1[ni];
                g_Y[((size_t)(b*49 + t1))*HWX + pB] = d3[ni];
            }
        }
    }
}

// ---------------------------------------------------------------------------
// K5: final: sw = sigmoid(sum_tap Y[p+Delta,tap] + b); out = h*cw*sw
// 256 thr, thread = pixel; grid BB*HWX/256
// ---------------------------------------------------------------------------
__global__ __launch_bounds__(256) void final_kernel(
        const float* __restrict__ sa_b, float* __restrict__ out) {
    __shared__ float cws[CC];
    const int idx = blockIdx.x*256 + threadIdx.x;
    const int b = idx / HWX;
    const int p = idx % HWX;
    const int y = p / WW, x = p % WW;

    if (threadIdx.x < CC) cws[threadIdx.x] = g_cw[b*CC + threadIdx.x];
    __syncthreads();

    float acc = sa_b[0];
    const float* Yb = g_Y + (size_t)b*49*HWX;
    #pragma unroll
    for (int dy = 0; dy < 7; ++dy) {
        int yy = y + dy - 3;
        if ((unsigned)yy >= (unsigned)HH) continue;
        #pragma unroll
        for (int dx = 0; dx < 7; ++dx) {
            int xx = x + dx - 3;
            if ((unsigned)xx >= (unsigned)WW) continue;
            acc += Yb[(size_t)(dy*7 + dx)*HWX + yy*WW + xx];
        }
    }
    float sw = 1.f / (1.f + expf(-acc));

    const float* hb = g_h + (size_t)b*CC*HWX + p;
    float* ob = out + (size_t)b*CC*HWX + p;
    #pragma unroll 8
    for (int c = 0; c < CC; ++c)
        ob[(size_t)c*HWX] = hb[(size_t)c*HWX] * cws[c] * sw;
}

// ---------------------------------------------------------------------------
extern "C" void kernel_launch(void* const* d_in, const int* in_sizes, int n_in,
                              void* d_out, int out_size) {
    const float* x      = (const float*)d_in[0];
    const float* off_w  = (const float*)d_in[1];
    const float* off_b  = (const float*)d_in[2];
    const float* dw     = (const float*)d_in[3];
    const float* db     = (const float*)d_in[4];
    const float* bn_g   = (const float*)d_in[5];
    const float* bn_b   = (const float*)d_in[6];
    const float* bn_m   = (const float*)d_in[7];
    const float* bn_v   = (const float*)d_in[8];
    const float* ca_w1  = (const float*)d_in[9];
    const float* ca_b1  = (const float*)d_in[10];
    const float* ca_w2  = (const float*)d_in[11];
    const float* ca_b2  = (const float*)d_in[12];
    const float* sa_w   = (const float*)d_in[13];
    const float* sa_b   = (const float*)d_in[14];
    float* out = (float*)d_out;

    transpose_w_kernel<<<(9*CC*CC + 8*24*76 + 255)/256, 256>>>(dw, off_w);
    nhwc_kernel       <<<BB*HWX/32, 256>>>(x);
    offset_conv_kernel<<<dim3(WW/64, HH/8, BB), 256>>>(x, off_b);
    deform_bn_kernel  <<<dim3(WW/64, HH, BB), 256>>>(db, bn_g, bn_b, bn_m, bn_v);
    ca_kernel         <<<1, 256>>>(ca_w1, ca_b1, ca_w2, ca_b2);
    y_gemm_kernel     <<<dim3(HWX/64, BB), 256>>>(sa_w);
    final_kernel      <<<BB*HWX/256, 256>>>(sa_b, out);
}

// round 14
// speedup vs baseline: 3.9717x; 1.1897x over previous
#include <cuda_runtime.h>
#include <cuda_fp16.h>
#include <math.h>
#include <stdint.h>

#define BB   4
#define CC   64
#define HH   192
#define WW   192
#define HWX  (HH*WW)
#define OFFC 18
#define HID  4

// warp-level f16 MMA, fp32 accumulate: D(16x8) += A(16x16) * B(16x8)
#define MMA_F16(d0,d1,d2,d3, a0,a1,a2,a3, b0,b1)                               \
    asm volatile("mma.sync.aligned.m16n8k16.row.col.f32.f16.f16.f32 "          \
        "{%0,%1,%2,%3}, {%4,%5,%6,%7}, {%8,%9}, {%0,%1,%2,%3};"                \
        : "+f"(d0), "+f"(d1), "+f"(d2), "+f"(d3)                               \
        : "r"(a0), "r"(a1), "r"(a2), "r"(a3), "r"(b0), "r"(b1))

// scratch (device globals; allocations are forbidden)
__device__ float g_off[BB*OFFC*HH*WW];            // 10.6 MB
__device__ float g_h  [BB*CC*HH*WW];              // 37.7 MB
__device__ __align__(16) __half g_xTh[BB*HWX*CC]; // 18.9 MB NHWC fp16 x
__device__ __half g_Yh[BB*49*HWX];                // 14.5 MB tap maps (fp16)
__device__ float g_pool[BB*CC];
__device__ float g_cw  [BB*CC];
__device__ __align__(16) __half g_dwTh[9*CC*CC];  // [kk][o][c] fp16
__device__ __align__(16) uint32_t g_offwH[9*24*36]; // [tap][o(24)][word36] half2

// offset-conv v3 smem (words): halo [396][36] + B [9*24][36]
#define OC_HALO_W (396*36)
#define OC_B_W    (9*24*36)
#define OC_SMEM_BYTES ((OC_HALO_W + OC_B_W)*4)    // 88128

// ---------------------------------------------------------------------------
// K0: weight prep
// ---------------------------------------------------------------------------
__global__ __launch_bounds__(256) void transpose_w_kernel(
        const float* __restrict__ dw, const float* __restrict__ off_w) {
    int d = blockIdx.x*256 + threadIdx.x;
    if (blockIdx.x == 0) g_pool[threadIdx.x] = 0.f;
    if (d < 9*CC*CC) {
        int kk = d >> 12;
        int o  = (d >> 6) & 63;
        int c  = d & 63;
        g_dwTh[d] = __float2half_rn(dw[(o*CC + c)*9 + kk]);
    } else {
        int e = d - 9*CC*CC;
        if (e < 9*24*36) {
            int tap = e / (24*36);
            int rem = e % (24*36);
            int o   = rem / 36;
            int w   = rem % 36;
            __half2 v = __half2half2(__float2half(0.f));
            if (o < OFFC && w < 32)
                v = __floats2half2_rn(off_w[(o*CC + 2*w    )*9 + tap],
                                      off_w[(o*CC + 2*w + 1)*9 + tap]);
            g_offwH[e] = *(const uint32_t*)&v;
        }
    }
}

// ---------------------------------------------------------------------------
// K0b: NCHW fp32 -> NHWC fp16 transpose of x
// ---------------------------------------------------------------------------
__global__ __launch_bounds__(256) void nhwc_kernel(const float* __restrict__ x) {
    __shared__ float ts[64*33];
    const int tid = threadIdx.x;
    const int blk = blockIdx.x;
    const int b   = blk / (HWX/32);
    const int pt  = (blk % (HWX/32)) * 32;
    const int px5 = tid & 31, cg = tid >> 5;

    #pragma unroll
    for (int it = 0; it < 8; ++it) {
        int ch = it*8 + cg;
        ts[ch*33 + px5] = x[((size_t)(b*CC + ch))*HWX + pt + px5];
    }
    __syncthreads();
    const int px = tid >> 3;
    const int g  = tid & 7;
    uint4 o;
    uint32_t* ow = (uint32_t*)&o;
    #pragma unroll
    for (int p2 = 0; p2 < 4; ++p2) {
        __half2 h = __floats2half2_rn(ts[(g*8 + 2*p2)*33 + px],
                                      ts[(g*8 + 2*p2 + 1)*33 + px]);
        ow[p2] = *(uint32_t*)&h;
    }
    ((uint4*)g_xTh)[((size_t)b*HWX + pt + px)*8 + g] = o;
}

// ---------------------------------------------------------------------------
// K1 v3: 3x3 conv 64 -> 18 via f16 MMA from NHWC fp16 halo.
// block = 64x4 = 256 px (M), 24 outch (N, 18 live), K=64 per tap x 9 taps.
// 256 threads (8 warps; warp owns 2 m-tiles x 3 n-tiles).
// grid (3, 48, 4); dynamic smem 88 KB
// ---------------------------------------------------------------------------
__global__ __launch_bounds__(256) void offset_conv_kernel(
        const float* __restrict__ off_b) {
    extern __shared__ uint32_t osm[];
    uint32_t* halo = osm;               // [pos 0..395][36 words]
    uint32_t* Bs   = osm + OC_HALO_W;   // [tap*24+o][36 words]

    const int tid = threadIdx.x;
    const int wid = tid >> 5, lid = tid & 31;
    const int bx = blockIdx.x, by = blockIdx.y, b = blockIdx.z;
    const int r4 = lid >> 2, klo = lid & 3;

    // stage halo: 396 positions x 64 ch fp16, coalesced uint4
    {
        const uint4* xs = (const uint4*)g_xTh + (size_t)b*HWX*8;
        for (int t = tid; t < 396*8; t += 256) {
            int pos = t >> 3, c8 = t & 7;
            int rr = pos / 66, q = pos % 66;
            int gy = by*4 + rr - 1, gx = bx*64 + q - 1;
            uint4 v = make_uint4(0u, 0u, 0u, 0u);
            if ((unsigned)gy < (unsigned)HH && (unsigned)gx < (unsigned)WW)
                v = xs[((size_t)gy*WW + gx)*8 + c8];
            *(uint4*)(halo + pos*36 + c8*4) = v;
        }
    }
    // stage B panels
    for (int t = tid; t < 9*24*9; t += 256)
        ((uint4*)Bs)[t] = ((const uint4*)g_offwH)[t];
    __syncthreads();

    float d[2][3][4];
    #pragma unroll
    for (int mt2 = 0; mt2 < 2; ++mt2)
        #pragma unroll
        for (int nt = 0; nt < 3; ++nt)
            { d[mt2][nt][0]=0.f; d[mt2][nt][1]=0.f; d[mt2][nt][2]=0.f; d[mt2][nt][3]=0.f; }

    const int mtA = wid*2;
    #pragma unroll
    for (int tap = 0; tap < 9; ++tap) {
        const int i = tap/3, j = tap%3;
        #pragma unroll
        for (int s = 0; s < 4; ++s) {
            const int kw = s*8 + klo;
            uint32_t a[2][4];
            #pragma unroll
            for (int mt2 = 0; mt2 < 2; ++mt2) {
                int m = (mtA + mt2)*16 + r4;
                int pos = ((m >> 6) + i)*66 + (m & 63) + j;
                a[mt2][0] = halo[ pos     *36 + kw    ];
                a[mt2][1] = halo[(pos + 8)*36 + kw    ];
                a[mt2][2] = halo[ pos     *36 + kw + 4];
                a[mt2][3] = halo[(pos + 8)*36 + kw + 4];
            }
            #pragma unroll
            for (int nt = 0; nt < 3; ++nt) {
                uint32_t b0 = Bs[(tap*24 + nt*8 + r4)*36 + kw];
                uint32_t b1 = Bs[(tap*24 + nt*8 + r4)*36 + kw + 4];
                MMA_F16(d[0][nt][0], d[0][nt][1], d[0][nt][2], d[0][nt][3],
                        a[0][0], a[0][1], a[0][2], a[0][3], b0, b1);
                MMA_F16(d[1][nt][0], d[1][nt][1], d[1][nt][2], d[1][nt][3],
                        a[1][0], a[1][1], a[1][2], a[1][3], b0, b1);
            }
        }
    }

    // epilogue: bias + store offsets
    #pragma unroll
    for (int mt2 = 0; mt2 < 2; ++mt2) {
        int m0 = (mtA + mt2)*16 + r4;
        int y0 = by*4 + (m0 >> 6), x0 = bx*64 + (m0 & 63);
        #pragma unroll
        for (int nt = 0; nt < 3; ++nt) {
            int o0 = nt*8 + 2*klo, o1 = o0 + 1;
            if (o0 < OFFC) {
                float bv = off_b[o0];
                float* dst = &g_off[((size_t)(b*OFFC + o0)*HH + y0)*WW + x0];
                dst[0] = d[mt2][nt][0] + bv;
                dst[8] = d[mt2][nt][2] + bv;
            }
            if (o1 < OFFC) {
                float bv = off_b[o1];
                float* dst = &g_off[((size_t)(b*OFFC + o1)*HH + y0)*WW + x0];
                dst[0] = d[mt2][nt][1] + bv;
                dst[8] = d[mt2][nt][3] + bv;
            }
        }
    }
}

// ---------------------------------------------------------------------------
// K2: deformable conv via f16 mma (fp32 accum), pipelined (R12, validated)
// ---------------------------------------------------------------------------
__global__ __launch_bounds__(256, 3) void deform_bn_kernel(
        const float* __restrict__ db,
        const float* __restrict__ gma,
        const float* __restrict__ bta,
        const float* __restrict__ mean,
        const float* __restrict__ var) {
    __shared__ uint32_t A_s[2][64*36];
    __shared__ uint32_t B_s[2][64*36];
    __shared__ float    M_s[2][512];
    __shared__ float    sc_s[64], sh_s[64];

    const int tid = threadIdx.x;
    const int wid = tid >> 5, lid = tid & 31;
    const int b   = blockIdx.z;
    const int y   = blockIdx.y;
    const int x0b = blockIdx.x * 64;

    if (tid < 64) {
        float sc = gma[tid] * rsqrtf(var[tid] + 1e-5f);
        sc_s[tid] = sc;
        sh_s[tid] = (db[tid] - mean[tid])*sc + bta[tid];
    }

    const __half* xh = g_xTh + (size_t)b*HWX*CC;

    auto compute_meta = [&](int kk, int mb) {
        if (tid < 64) {
            int xx = x0b + tid;
            int i = kk/3, j = kk%3;
            float oy = g_off[((size_t)(b*OFFC + 2*kk  )*HH + y)*WW + xx];
            float ox = g_off[((size_t)(b*OFFC + 2*kk+1)*HH + y)*WW + xx];
            float py = (float)(y  + i - 1) + oy;
            float px = (float)(xx + j - 1) + ox;
            float fy = floorf(py), fx = floorf(px);
            int yq = (int)fy, xq = (int)fx;
            float wy = py - fy, wx = px - fx;
            float vy0 = ((unsigned)yq     < (unsigned)HH) ? 1.f : 0.f;
            float vy1 = ((unsigned)(yq+1) < (unsigned)HH) ? 1.f : 0.f;
            float vx0 = ((unsigned)xq     < (unsigned)WW) ? 1.f : 0.f;
            float vx1 = ((unsigned)(xq+1) < (unsigned)WW) ? 1.f : 0.f;
            float uA = (1.f - wy)*vy0, uB = wy*vy1;
            float wA = (1.f - wx)*vx0, wB = wx*vx1;
            int yb0 = min(max(yq,   0), HH-1);
            int yb1 = min(max(yq+1, 0), HH-1);
            int xc0 = min(max(xq,   0), WW-1);
            int xc1 = min(max(xq+1, 0), WW-1);
            float* mp = M_s[mb] + tid*8;
            mp[0] = __uint_as_float((uint32_t)((yb0*WW + xc0)*CC));
            mp[1] = __uint_as_float((uint32_t)((yb1*WW + xc0)*CC));
            mp[2] = __uint_as_float((uint32_t)((xc1 - xc0)*CC));
            mp[3] = uA; mp[4] = uB; mp[5] = wA; mp[6] = wB; mp[7] = 0.f;
        }
    };
    auto stage_B = [&](int kk, int bf) {
        const uint4* src = (const uint4*)(g_dwTh + kk*4096);
        #pragma unroll 2
        for (int t = tid; t < 512; t += 256) {
            int o = t >> 3, w4 = t & 7;
            ((uint4*)(&B_s[bf][o*36]))[w4] = src[o*8 + w4];
        }
    };
    auto gather = [&](int abuf, int mb) {
        const int c8 = lid & 7, pq = lid >> 3;
        #pragma unroll
        for (int it = 0; it < 2; ++it) {
            int px = (wid << 3) + (it << 2) + pq;
            const float* mp = M_s[mb] + px*8;
            float4 m0 = *(const float4*)mp;
            float4 m1 = *(const float4*)(mp + 4);
            uint32_t base0 = __float_as_uint(m0.x);
            uint32_t base1 = __float_as_uint(m0.y);
            uint32_t dx    = __float_as_uint(m0.z);
            float uA = m0.w, uB = m1.x, wA = m1.y, wB = m1.z;
            uint4 cA0 = ((const uint4*)(xh + base0     ))[c8];
            uint4 cA1 = ((const uint4*)(xh + base0 + dx))[c8];
            uint4 cB0 = ((const uint4*)(xh + base1     ))[c8];
            uint4 cB1 = ((const uint4*)(xh + base1 + dx))[c8];
            const uint32_t* wa0 = (const uint32_t*)&cA0;
            const uint32_t* wa1 = (const uint32_t*)&cA1;
            const uint32_t* wb0 = (const uint32_t*)&cB0;
            const uint32_t* wb1 = (const uint32_t*)&cB1;
            uint4 out;
            uint32_t* ow = (uint32_t*)&out;
            #pragma unroll
            for (int p = 0; p < 4; ++p) {
                float2 fa0 = __half22float2(*(const __half2*)&wa0[p]);
                float2 fa1 = __half22float2(*(const __half2*)&wa1[p]);
                float2 fb0 = __half22float2(*(const __half2*)&wb0[p]);
                float2 fb1 = __half22float2(*(const __half2*)&wb1[p]);
                float t0x = uA*fa0.x + uB*fb0.x, t1x = uA*fa1.x + uB*fb1.x;
                float t0y = uA*fa0.y + uB*fb0.y, t1y = uA*fa1.y + uB*fb1.y;
                __half2 h = __floats2half2_rn(wA*t0x + wB*t1x, wA*t0y + wB*t1y);
                ow[p] = *(const uint32_t*)&h;
            }
            ((uint4*)(&A_s[abuf][px*36]))[c8] = out;
        }
    };

    float d[2][2][4];
    #pragma unroll
    for (int mt = 0; mt < 2; ++mt)
        #pragma unroll
        for (int nt = 0; nt < 2; ++nt)
            { d[mt][nt][0]=0.f; d[mt][nt][1]=0.f; d[mt][nt][2]=0.f; d[mt][nt][3]=0.f; }

    const int mg = wid & 1, ng = wid >> 1;
    const int r4 = lid >> 2, klo = lid & 3;

    compute_meta(0, 0);
    __syncthreads();
    stage_B(0, 0);
    gather(0, 0);
    compute_meta(1, 1);
    __syncthreads();

    #pragma unroll 1
    for (int kk = 0; kk < 9; ++kk) {
        const int buf = kk & 1, nxt = buf ^ 1;
        if (kk < 8) {
            stage_B(kk + 1, nxt);
            if (kk < 7) compute_meta(kk + 2, buf);
            gather(nxt, nxt);
        }
        {
            const uint32_t* Ab = A_s[buf];
            const uint32_t* Bb = B_s[buf];
            #pragma unroll
            for (int s = 0; s < 4; ++s) {
                const int kw = s*8 + klo;
                uint32_t a[2][4];
                #pragma unroll
                for (int mt = 0; mt < 2; ++mt) {
                    const int row = (mg*2 + mt)*16 + r4;
                    a[mt][0] = Ab[ row     *36 + kw    ];
                    a[mt][1] = Ab[(row + 8)*36 + kw    ];
                    a[mt][2] = Ab[ row     *36 + kw + 4];
                    a[mt][3] = Ab[(row + 8)*36 + kw + 4];
                }
                #pragma unroll
                for (int nt = 0; nt < 2; ++nt) {
                    const int orow = (ng*2 + nt)*8 + r4;
                    uint32_t b0 = Bb[orow*36 + kw];
                    uint32_t b1 = Bb[orow*36 + kw + 4];
                    MMA_F16(d[0][nt][0], d[0][nt][1], d[0][nt][2], d[0][nt][3],
                            a[0][0], a[0][1], a[0][2], a[0][3], b0, b1);
                    MMA_F16(d[1][nt][0], d[1][nt][1], d[1][nt][2], d[1][nt][3],
                            a[1][0], a[1][1], a[1][2], a[1][3], b0, b1);
                }
            }
        }
        __syncthreads();
    }

    #pragma unroll
    for (int nt = 0; nt < 2; ++nt) {
        const int o0 = (ng*2 + nt)*8 + klo*2;
        const int o1 = o0 + 1;
        const float sc0 = sc_s[o0], sh0 = sh_s[o0];
        const float sc1 = sc_s[o1], sh1 = sh_s[o1];
        float s0 = 0.f, s1 = 0.f;
        #pragma unroll
        for (int mt = 0; mt < 2; ++mt) {
            const int p0 = (mg*2 + mt)*16 + r4, p1 = p0 + 8;
            float v00 = d[mt][nt][0]*sc0 + sh0;
            float v01 = d[mt][nt][1]*sc1 + sh1;
            float v10 = d[mt][nt][2]*sc0 + sh0;
            float v11 = d[mt][nt][3]*sc1 + sh1;
            g_h[((size_t)(b*CC + o0)*HH + y)*WW + x0b + p0] = v00;
            g_h[((size_t)(b*CC + o1)*HH + y)*WW + x0b + p0] = v01;
            g_h[((size_t)(b*CC + o0)*HH + y)*WW + x0b + p1] = v10;
            g_h[((size_t)(b*CC + o1)*HH + y)*WW + x0b + p1] = v11;
            s0 += v00 + v10;
            s1 += v01 + v11;
        }
        #pragma unroll
        for (int off = 4; off < 32; off <<= 1) {
            s0 += __shfl_xor_sync(0xffffffffu, s0, off);
            s1 += __shfl_xor_sync(0xffffffffu, s1, off);
        }
        if (r4 == 0) {
            atomicAdd(&g_pool[b*CC + o0], s0);
            atomicAdd(&g_pool[b*CC + o1], s1);
        }
    }
}

// ---------------------------------------------------------------------------
// K3: SE MLP (hid=4)
// ---------------------------------------------------------------------------
__global__ __launch_bounds__(256) void ca_kernel(
        const float* __restrict__ w1, const float* __restrict__ b1,
        const float* __restrict__ w2, const float* __restrict__ b2) {
    __shared__ float t[BB*HID];
    const int tid = threadIdx.x;
    const int b = tid >> 6, c = tid & 63;
    if (c < HID) {
        float s = b1[c];
        for (int cc = 0; cc < CC; ++cc)
            s += w1[c*CC + cc] * (g_pool[b*CC + cc] * (1.f/(float)HWX));
        t[b*HID + c] = fmaxf(s, 0.f);
    }
    __syncthreads();
    float s = b2[c];
    #pragma unroll
    for (int h = 0; h < HID; ++h) s += w2[c*HID + h] * t[b*HID + h];
    g_cw[tid] = 1.f / (1.f + expf(-s));
}

// ---------------------------------------------------------------------------
// K4: Y GEMM: Y[p, tap] = sum_c (sa_w[c,tap]*cw[c]) * h[c,p]
// ---------------------------------------------------------------------------
__global__ __launch_bounds__(256) void y_gemm_kernel(
        const float* __restrict__ sa_w) {
    __shared__ uint32_t A_s[64*36];
    __shared__ uint32_t B_s[56*36];
    __shared__ float ts[64*33];

    const int tid = threadIdx.x;
    const int wid = tid >> 5, lid = tid & 31;
    const int b   = blockIdx.y;
    const int p0b = blockIdx.x * 64;

    for (int e = tid; e < 56*32; e += 256) {
        int tap = e >> 5, c2 = e & 31;
        __half2 v = __half2half2(__float2half(0.f));
        if (tap < 49) {
            float w0 = sa_w[(2*c2  )*49 + tap] * g_cw[b*CC + 2*c2];
            float w1 = sa_w[(2*c2+1)*49 + tap] * g_cw[b*CC + 2*c2 + 1];
            v = __floats2half2_rn(w0, w1);
        }
        B_s[tap*36 + c2] = *(const uint32_t*)&v;
    }

    const int px5 = tid & 31, cg = tid >> 5;
    #pragma unroll
    for (int sub = 0; sub < 2; ++sub) {
        __syncthreads();
        #pragma unroll
        for (int it = 0; it < 8; ++it) {
            int ch = it*8 + cg;
            ts[ch*33 + px5] = g_h[((size_t)(b*CC + ch))*HWX + p0b + sub*32 + px5];
        }
        __syncthreads();
        const int c2 = tid & 31;
        #pragma unroll
        for (int it = 0; it < 4; ++it) {
            int pl = it*8 + (tid >> 5);
            __half2 h = __floats2half2_rn(ts[(2*c2)*33 + pl], ts[(2*c2+1)*33 + pl]);
            A_s[(sub*32 + pl)*36 + c2] = *(const uint32_t*)&h;
        }
    }
    __syncthreads();

    const int mt = wid & 3, ng = wid >> 2;
    const int r4 = lid >> 2, klo = lid & 3;
    const int nt0 = ng*4, ntn = ng ? 3 : 4;

    float d0[4], d1[4], d2[4], d3[4];
    #pragma unroll
    for (int i = 0; i < 4; ++i) { d0[i]=0.f; d1[i]=0.f; d2[i]=0.f; d3[i]=0.f; }

    #pragma unroll
    for (int s = 0; s < 4; ++s) {
        const int kw = s*8 + klo;
        const int row = mt*16 + r4;
        uint32_t a0 = A_s[ row     *36 + kw    ];
        uint32_t a1 = A_s[(row + 8)*36 + kw    ];
        uint32_t a2 = A_s[ row     *36 + kw + 4];
        uint32_t a3 = A_s[(row + 8)*36 + kw + 4];
        #pragma unroll
        for (int ni = 0; ni < 4; ++ni) {
            if (ni < ntn) {
                const int orow = (nt0 + ni)*8 + r4;
                uint32_t b0 = B_s[orow*36 + kw];
                uint32_t b1 = B_s[orow*36 + kw + 4];
                MMA_F16(d0[ni], d1[ni], d2[ni], d3[ni], a0, a1, a2, a3, b0, b1);
            }
        }
    }

    const int pA = p0b + mt*16 + r4;
    const int pB = pA + 8;
    #pragma unroll
    for (int ni = 0; ni < 4; ++ni) {
        if (ni < ntn) {
            int t0 = (nt0 + ni)*8 + klo*2;
            int t1 = t0 + 1;
            if (t0 < 49) {
                g_Yh[((size_t)(b*49 + t0))*HWX + pA] = __float2half(d0[ni]);
                g_Yh[((size_t)(b*49 + t0))*HWX + pB] = __float2half(d2[ni]);
            }
            if (t1 < 49) {
                g_Yh[((size_t)(b*49 + t1))*HWX + pA] = __float2half(d1[ni]);
                g_Yh[((size_t)(b*49 + t1))*HWX + pB] = __float2half(d3[ni]);
            }
        }
    }
}

// ---------------------------------------------------------------------------
// K5: final: sw = sigmoid(sum_tap Y[p+Delta,tap] + b); out = h*cw*sw
// ---------------------------------------------------------------------------
__global__ __launch_bounds__(256) void final_kernel(
        const float* __restrict__ sa_b, float* __restrict__ out) {
    __shared__ float cws[CC];
    const int idx = blockIdx.x*256 + threadIdx.x;
    const int b = idx / HWX;
    const int p = idx % HWX;
    const int y = p / WW, x = p % WW;

    if (threadIdx.x < CC) cws[threadIdx.x] = g_cw[b*CC + threadIdx.x];
    __syncthreads();

    float acc = sa_b[0];
    const __half* Yb = g_Yh + (size_t)b*49*HWX;
    #pragma unroll
    for (int dy = 0; dy < 7; ++dy) {
        int yy = y + dy - 3;
        if ((unsigned)yy >= (unsigned)HH) continue;
        #pragma unroll
        for (int dx = 0; dx < 7; ++dx) {
            int xx = x + dx - 3;
            if ((unsigned)xx >= (unsigned)WW) continue;
            acc += __half2float(Yb[(size_t)(dy*7 + dx)*HWX + yy*WW + xx]);
        }
    }
    float sw = 1.f / (1.f + expf(-acc));

    const float* hb = g_h + (size_t)b*CC*HWX + p;
    float* ob = out + (size_t)b*CC*HWX + p;
    #pragma unroll 8
    for (int c = 0; c < CC; ++c)
        ob[(size_t)c*HWX] = hb[(size_t)c*HWX] * cws[c] * sw;
}

// ---------------------------------------------------------------------------
extern "C" void kernel_launch(void* const* d_in, const int* in_sizes, int n_in,
                              void* d_out, int out_size) {
    const float* x      = (const float*)d_in[0];
    const float* off_w  = (const float*)d_in[1];
    const float* off_b  = (const float*)d_in[2];
    const float* dw     = (const float*)d_in[3];
    const float* db     = (const float*)d_in[4];
    const float* bn_g   = (const float*)d_in[5];
    const float* bn_b   = (const float*)d_in[6];
    const float* bn_m   = (const float*)d_in[7];
    const float* bn_v   = (const float*)d_in[8];
    const float* ca_w1  = (const float*)d_in[9];
    const float* ca_b1  = (const float*)d_in[10];
    const float* ca_w2  = (const float*)d_in[11];
    const float* ca_b2  = (const float*)d_in[12];
    const float* sa_w   = (const float*)d_in[13];
    const float* sa_b   = (const float*)d_in[14];
    float* out = (float*)d_out;

    cudaFuncSetAttribute(offset_conv_kernel,
                         cudaFuncAttributeMaxDynamicSharedMemorySize,
                         OC_SMEM_BYTES);

    transpose_w_kernel<<<(9*CC*CC + 9*24*36 + 255)/256, 256>>>(dw, off_w);
    nhwc_kernel       <<<BB*HWX/32, 256>>>(x);
    offset_conv_kernel<<<dim3(WW/64, HH/4, BB), 256, OC_SMEM_BYTES>>>(off_b);
    deform_bn_kernel  <<<dim3(WW/64, HH, BB), 256>>>(db, bn_g, bn_b, bn_m, bn_v);
    ca_kernel         <<<1, 256>>>(ca_w1, ca_b1, ca_w2, ca_b2);
    y_gemm_kernel     <<<dim3(HWX/64, BB), 256>>>(sa_w);
    final_kernel      <<<BB*HWX/256, 256>>>(sa_b, out);
}

// round 15
// speedup vs baseline: 4.0874x; 1.0291x over previous
#include <cuda_runtime.h>
#include <cuda_fp16.h>
#include <math.h>
#include <stdint.h>

#define BB   4
#define CC   64
#define HH   192
#define WW   192
#define HWX  (HH*WW)
#define OFFC 18
#define HID  4

// warp-level f16 MMA, fp32 accumulate: D(16x8) += A(16x16) * B(16x8)
#define MMA_F16(d0,d1,d2,d3, a0,a1,a2,a3, b0,b1)                               \
    asm volatile("mma.sync.aligned.m16n8k16.row.col.f32.f16.f16.f32 "          \
        "{%0,%1,%2,%3}, {%4,%5,%6,%7}, {%8,%9}, {%0,%1,%2,%3};"                \
        : "+f"(d0), "+f"(d1), "+f"(d2), "+f"(d3)                               \
        : "r"(a0), "r"(a1), "r"(a2), "r"(a3), "r"(b0), "r"(b1))

#define LDSM_X4(r0,r1,r2,r3,a)                                                 \
    asm volatile("ldmatrix.sync.aligned.m8n8.x4.shared.b16 {%0,%1,%2,%3}, [%4];" \
        : "=r"(r0), "=r"(r1), "=r"(r2), "=r"(r3) : "r"(a))
#define LDSM_X2(r0,r1,a)                                                       \
    asm volatile("ldmatrix.sync.aligned.m8n8.x2.shared.b16 {%0,%1}, [%2];"     \
        : "=r"(r0), "=r"(r1) : "r"(a))

__device__ __forceinline__ uint32_t smaddr(const void* p) {
    return (uint32_t)__cvta_generic_to_shared(p);
}

// scratch (device globals; allocations are forbidden)
__device__ float g_off[BB*OFFC*HH*WW];            // 10.6 MB
__device__ float g_h  [BB*CC*HH*WW];              // 37.7 MB
__device__ __align__(16) __half g_xTh[BB*HWX*CC]; // 18.9 MB NHWC fp16 x
__device__ __half g_Yh[BB*49*HWX];                // 14.5 MB tap maps (fp16)
__device__ float g_pool[BB*CC];
__device__ float g_cw  [BB*CC];
__device__ __align__(16) __half g_dwTh[9*CC*CC];  // [kk][o][c] fp16
__device__ __align__(16) uint32_t g_offwH[9*24*36]; // [tap][o(24)][word36] half2

// offset-conv v3 smem (words): halo [396][36] + B [9*24][36]
#define OC_HALO_W (396*36)
#define OC_B_W    (9*24*36)
#define OC_SMEM_BYTES ((OC_HALO_W + OC_B_W)*4)    // 88128

// ---------------------------------------------------------------------------
// K0: weight prep
// ---------------------------------------------------------------------------
__global__ __launch_bounds__(256) void transpose_w_kernel(
        const float* __restrict__ dw, const float* __restrict__ off_w) {
    int d = blockIdx.x*256 + threadIdx.x;
    if (blockIdx.x == 0) g_pool[threadIdx.x] = 0.f;
    if (d < 9*CC*CC) {
        int kk = d >> 12;
        int o  = (d >> 6) & 63;
        int c  = d & 63;
        g_dwTh[d] = __float2half_rn(dw[(o*CC + c)*9 + kk]);
    } else {
        int e = d - 9*CC*CC;
        if (e < 9*24*36) {
            int tap = e / (24*36);
            int rem = e % (24*36);
            int o   = rem / 36;
            int w   = rem % 36;
            __half2 v = __half2half2(__float2half(0.f));
            if (o < OFFC && w < 32)
                v = __floats2half2_rn(off_w[(o*CC + 2*w    )*9 + tap],
                                      off_w[(o*CC + 2*w + 1)*9 + tap]);
            g_offwH[e] = *(const uint32_t*)&v;
        }
    }
}

// ---------------------------------------------------------------------------
// K0b: NCHW fp32 -> NHWC fp16 transpose of x
// ---------------------------------------------------------------------------
__global__ __launch_bounds__(256) void nhwc_kernel(const float* __restrict__ x) {
    __shared__ float ts[64*33];
    const int tid = threadIdx.x;
    const int blk = blockIdx.x;
    const int b   = blk / (HWX/32);
    const int pt  = (blk % (HWX/32)) * 32;
    const int px5 = tid & 31, cg = tid >> 5;

    #pragma unroll
    for (int it = 0; it < 8; ++it) {
        int ch = it*8 + cg;
        ts[ch*33 + px5] = x[((size_t)(b*CC + ch))*HWX + pt + px5];
    }
    __syncthreads();
    const int px = tid >> 3;
    const int g  = tid & 7;
    uint4 o;
    uint32_t* ow = (uint32_t*)&o;
    #pragma unroll
    for (int p2 = 0; p2 < 4; ++p2) {
        __half2 h = __floats2half2_rn(ts[(g*8 + 2*p2)*33 + px],
                                      ts[(g*8 + 2*p2 + 1)*33 + px]);
        ow[p2] = *(uint32_t*)&h;
    }
    ((uint4*)g_xTh)[((size_t)b*HWX + pt + px)*8 + g] = o;
}

// ---------------------------------------------------------------------------
// K1 v3: 3x3 conv 64 -> 18 via f16 MMA from NHWC fp16 halo (R14, validated)
// ---------------------------------------------------------------------------
__global__ __launch_bounds__(256) void offset_conv_kernel(
        const float* __restrict__ off_b) {
    extern __shared__ uint32_t osm[];
    uint32_t* halo = osm;               // [pos 0..395][36 words]
    uint32_t* Bs   = osm + OC_HALO_W;   // [tap*24+o][36 words]

    const int tid = threadIdx.x;
    const int wid = tid >> 5, lid = tid & 31;
    const int bx = blockIdx.x, by = blockIdx.y, b = blockIdx.z;
    const int r4 = lid >> 2, klo = lid & 3;

    {
        const uint4* xs = (const uint4*)g_xTh + (size_t)b*HWX*8;
        for (int t = tid; t < 396*8; t += 256) {
            int pos = t >> 3, c8 = t & 7;
            int rr = pos / 66, q = pos % 66;
            int gy = by*4 + rr - 1, gx = bx*64 + q - 1;
            uint4 v = make_uint4(0u, 0u, 0u, 0u);
            if ((unsigned)gy < (unsigned)HH && (unsigned)gx < (unsigned)WW)
                v = xs[((size_t)gy*WW + gx)*8 + c8];
            *(uint4*)(halo + pos*36 + c8*4) = v;
        }
    }
    for (int t = tid; t < 9*24*9; t += 256)
        ((uint4*)Bs)[t] = ((const uint4*)g_offwH)[t];
    __syncthreads();

    float d[2][3][4];
    #pragma unroll
    for (int mt2 = 0; mt2 < 2; ++mt2)
        #pragma unroll
        for (int nt = 0; nt < 3; ++nt)
            { d[mt2][nt][0]=0.f; d[mt2][nt][1]=0.f; d[mt2][nt][2]=0.f; d[mt2][nt][3]=0.f; }

    const int mtA = wid*2;
    #pragma unroll
    for (int tap = 0; tap < 9; ++tap) {
        const int i = tap/3, j = tap%3;
        #pragma unroll
        for (int s = 0; s < 4; ++s) {
            const int kw = s*8 + klo;
            uint32_t a[2][4];
            #pragma unroll
            for (int mt2 = 0; mt2 < 2; ++mt2) {
                int m = (mtA + mt2)*16 + r4;
                int pos = ((m >> 6) + i)*66 + (m & 63) + j;
                a[mt2][0] = halo[ pos     *36 + kw    ];
                a[mt2][1] = halo[(pos + 8)*36 + kw    ];
                a[mt2][2] = halo[ pos     *36 + kw + 4];
                a[mt2][3] = halo[(pos + 8)*36 + kw + 4];
            }
            #pragma unroll
            for (int nt = 0; nt < 3; ++nt) {
                uint32_t b0 = Bs[(tap*24 + nt*8 + r4)*36 + kw];
                uint32_t b1 = Bs[(tap*24 + nt*8 + r4)*36 + kw + 4];
                MMA_F16(d[0][nt][0], d[0][nt][1], d[0][nt][2], d[0][nt][3],
                        a[0][0], a[0][1], a[0][2], a[0][3], b0, b1);
                MMA_F16(d[1][nt][0], d[1][nt][1], d[1][nt][2], d[1][nt][3],
                        a[1][0], a[1][1], a[1][2], a[1][3], b0, b1);
            }
        }
    }

    #pragma unroll
    for (int mt2 = 0; mt2 < 2; ++mt2) {
        int m0 = (mtA + mt2)*16 + r4;
        int y0 = by*4 + (m0 >> 6), x0 = bx*64 + (m0 & 63);
        #pragma unroll
        for (int nt = 0; nt < 3; ++nt) {
            int o0 = nt*8 + 2*klo, o1 = o0 + 1;
            if (o0 < OFFC) {
                float bv = off_b[o0];
                float* dst = &g_off[((size_t)(b*OFFC + o0)*HH + y0)*WW + x0];
                dst[0] = d[mt2][nt][0] + bv;
                dst[8] = d[mt2][nt][2] + bv;
            }
            if (o1 < OFFC) {
                float bv = off_b[o1];
                float* dst = &g_off[((size_t)(b*OFFC + o1)*HH + y0)*WW + x0];
                dst[0] = d[mt2][nt][1] + bv;
                dst[8] = d[mt2][nt][3] + bv;
            }
        }
    }
}

// ---------------------------------------------------------------------------
// K2: deformable conv, f16 mma + ldmatrix + cp.async B staging
// ---------------------------------------------------------------------------
__global__ __launch_bounds__(256, 3) void deform_bn_kernel(
        const float* __restrict__ db,
        const float* __restrict__ gma,
        const float* __restrict__ bta,
        const float* __restrict__ mean,
        const float* __restrict__ var) {
    __shared__ uint32_t A_s[2][64*36];
    __shared__ uint32_t B_s[2][64*36];
    __shared__ float    M_s[2][512];
    __shared__ float    sc_s[64], sh_s[64];

    const int tid = threadIdx.x;
    const int wid = tid >> 5, lid = tid & 31;
    const int b   = blockIdx.z;
    const int y   = blockIdx.y;
    const int x0b = blockIdx.x * 64;

    if (tid < 64) {
        float sc = gma[tid] * rsqrtf(var[tid] + 1e-5f);
        sc_s[tid] = sc;
        sh_s[tid] = (db[tid] - mean[tid])*sc + bta[tid];
    }

    const __half* xh = g_xTh + (size_t)b*HWX*CC;

    auto compute_meta = [&](int kk, int mb) {
        if (tid < 64) {
            int xx = x0b + tid;
            int i = kk/3, j = kk%3;
            float oy = g_off[((size_t)(b*OFFC + 2*kk  )*HH + y)*WW + xx];
            float ox = g_off[((size_t)(b*OFFC + 2*kk+1)*HH + y)*WW + xx];
            float py = (float)(y  + i - 1) + oy;
            float px = (float)(xx + j - 1) + ox;
            float fy = floorf(py), fx = floorf(px);
            int yq = (int)fy, xq = (int)fx;
            float wy = py - fy, wx = px - fx;
            float vy0 = ((unsigned)yq     < (unsigned)HH) ? 1.f : 0.f;
            float vy1 = ((unsigned)(yq+1) < (unsigned)HH) ? 1.f : 0.f;
            float vx0 = ((unsigned)xq     < (unsigned)WW) ? 1.f : 0.f;
            float vx1 = ((unsigned)(xq+1) < (unsigned)WW) ? 1.f : 0.f;
            float uA = (1.f - wy)*vy0, uB = wy*vy1;
            float wA = (1.f - wx)*vx0, wB = wx*vx1;
            int yb0 = min(max(yq,   0), HH-1);
            int yb1 = min(max(yq+1, 0), HH-1);
            int xc0 = min(max(xq,   0), WW-1);
            int xc1 = min(max(xq+1, 0), WW-1);
            float* mp = M_s[mb] + tid*8;
            mp[0] = __uint_as_float((uint32_t)((yb0*WW + xc0)*CC));
            mp[1] = __uint_as_float((uint32_t)((yb1*WW + xc0)*CC));
            mp[2] = __uint_as_float((uint32_t)((xc1 - xc0)*CC));
            mp[3] = uA; mp[4] = uB; mp[5] = wA; mp[6] = wB; mp[7] = 0.f;
        }
    };
    auto stage_B = [&](int kk, int bf) {
        const uint4* src = (const uint4*)(g_dwTh + kk*4096);
        #pragma unroll 2
        for (int t = tid; t < 512; t += 256) {
            int o = t >> 3, w4 = t & 7;
            uint32_t dst = smaddr(&B_s[bf][o*36 + w4*4]);
            asm volatile("cp.async.ca.shared.global [%0], [%1], 16;"
                         :: "r"(dst), "l"(&src[o*8 + w4]) : "memory");
        }
        asm volatile("cp.async.commit_group;" ::: "memory");
    };
    auto gather = [&](int abuf, int mb) {
        const int c8 = lid & 7, pq = lid >> 3;
        #pragma unroll
        for (int it = 0; it < 2; ++it) {
            int px = (wid << 3) + (it << 2) + pq;
            const float* mp = M_s[mb] + px*8;
            float4 m0 = *(const float4*)mp;
            float4 m1 = *(const float4*)(mp + 4);
            uint32_t base0 = __float_as_uint(m0.x);
            uint32_t base1 = __float_as_uint(m0.y);
            uint32_t dx    = __float_as_uint(m0.z);
            float uA = m0.w, uB = m1.x, wA = m1.y, wB = m1.z;
            uint4 cA0 = ((const uint4*)(xh + base0     ))[c8];
            uint4 cA1 = ((const uint4*)(xh + base0 + dx))[c8];
            uint4 cB0 = ((const uint4*)(xh + base1     ))[c8];
            uint4 cB1 = ((const uint4*)(xh + base1 + dx))[c8];
            const uint32_t* wa0 = (const uint32_t*)&cA0;
            const uint32_t* wa1 = (const uint32_t*)&cA1;
            const uint32_t* wb0 = (const uint32_t*)&cB0;
            const uint32_t* wb1 = (const uint32_t*)&cB1;
            uint4 out;
            uint32_t* ow = (uint32_t*)&out;
            #pragma unroll
            for (int p = 0; p < 4; ++p) {
                float2 fa0 = __half22float2(*(const __half2*)&wa0[p]);
                float2 fa1 = __half22float2(*(const __half2*)&wa1[p]);
                float2 fb0 = __half22float2(*(const __half2*)&wb0[p]);
                float2 fb1 = __half22float2(*(const __half2*)&wb1[p]);
                float t0x = uA*fa0.x + uB*fb0.x, t1x = uA*fa1.x + uB*fb1.x;
                float t0y = uA*fa0.y + uB*fb0.y, t1y = uA*fa1.y + uB*fb1.y;
                __half2 h = __floats2half2_rn(wA*t0x + wB*t1x, wA*t0y + wB*t1y);
                ow[p] = *(const uint32_t*)&h;
            }
            ((uint4*)(&A_s[abuf][px*36]))[c8] = out;
        }
    };

    float d[2][2][4];
    #pragma unroll
    for (int mt = 0; mt < 2; ++mt)
        #pragma unroll
        for (int nt = 0; nt < 2; ++nt)
            { d[mt][nt][0]=0.f; d[mt][nt][1]=0.f; d[mt][nt][2]=0.f; d[mt][nt][3]=0.f; }

    const int mg = wid & 1, ng = wid >> 1;
    const int l8 = lid & 7, quad = lid >> 3;

    compute_meta(0, 0);
    __syncthreads();
    stage_B(0, 0);
    gather(0, 0);
    compute_meta(1, 1);
    asm volatile("cp.async.wait_group 0;" ::: "memory");
    __syncthreads();

    #pragma unroll 1
    for (int kk = 0; kk < 9; ++kk) {
        const int buf = kk & 1, nxt = buf ^ 1;
        if (kk < 8) {
            stage_B(kk + 1, nxt);
            if (kk < 7) compute_meta(kk + 2, buf);
            gather(nxt, nxt);
        }
        {
            const uint32_t* Ab = A_s[buf];
            const uint32_t* Bb = B_s[buf];
            // ldmatrix lane-address components
            const int arow_add = (quad & 1) ? 8 : 0;
            const int acol_add = (quad & 2) ? 4 : 0;
            const int bcol_add = (lid & 8) ? 4 : 0;
            #pragma unroll
            for (int s = 0; s < 4; ++s) {
                uint32_t a[2][4];
                #pragma unroll
                for (int mt = 0; mt < 2; ++mt) {
                    const int row = (mg*2 + mt)*16 + l8 + arow_add;
                    uint32_t addr = smaddr(&Ab[row*36 + s*8 + acol_add]);
                    LDSM_X4(a[mt][0], a[mt][1], a[mt][2], a[mt][3], addr);
                }
                #pragma unroll
                for (int nt = 0; nt < 2; ++nt) {
                    const int brow = (ng*2 + nt)*8 + l8;
                    uint32_t baddr = smaddr(&Bb[brow*36 + s*8 + bcol_add]);
                    uint32_t b0, b1;
                    LDSM_X2(b0, b1, baddr);
                    MMA_F16(d[0][nt][0], d[0][nt][1], d[0][nt][2], d[0][nt][3],
                            a[0][0], a[0][1], a[0][2], a[0][3], b0, b1);
                    MMA_F16(d[1][nt][0], d[1][nt][1], d[1][nt][2], d[1][nt][3],
                            a[1][0], a[1][1], a[1][2], a[1][3], b0, b1);
                }
            }
        }
        if (kk < 8) asm volatile("cp.async.wait_group 0;" ::: "memory");
        __syncthreads();
    }

    const int r4 = lid >> 2, klo = lid & 3;
    #pragma unroll
    for (int nt = 0; nt < 2; ++nt) {
        const int o0 = (ng*2 + nt)*8 + klo*2;
        const int o1 = o0 + 1;
        const float sc0 = sc_s[o0], sh0 = sh_s[o0];
        const float sc1 = sc_s[o1], sh1 = sh_s[o1];
        float s0 = 0.f, s1 = 0.f;
        #pragma unroll
        for (int mt = 0; mt < 2; ++mt) {
            const int p0 = (mg*2 + mt)*16 + r4, p1 = p0 + 8;
            float v00 = d[mt][nt][0]*sc0 + sh0;
            float v01 = d[mt][nt][1]*sc1 + sh1;
            float v10 = d[mt][nt][2]*sc0 + sh0;
            float v11 = d[mt][nt][3]*sc1 + sh1;
            g_h[((size_t)(b*CC + o0)*HH + y)*WW + x0b + p0] = v00;
            g_h[((size_t)(b*CC + o1)*HH + y)*WW + x0b + p0] = v01;
            g_h[((size_t)(b*CC + o0)*HH + y)*WW + x0b + p1] = v10;
            g_h[((size_t)(b*CC + o1)*HH + y)*WW + x0b + p1] = v11;
            s0 += v00 + v10;
            s1 += v01 + v11;
        }
        #pragma unroll
        for (int off = 4; off < 32; off <<= 1) {
            s0 += __shfl_xor_sync(0xffffffffu, s0, off);
            s1 += __shfl_xor_sync(0xffffffffu, s1, off);
        }
        if (r4 == 0) {
            atomicAdd(&g_pool[b*CC + o0], s0);
            atomicAdd(&g_pool[b*CC + o1], s1);
        }
    }
}

// ---------------------------------------------------------------------------
// K3: SE MLP (hid=4)
// ---------------------------------------------------------------------------
__global__ __launch_bounds__(256) void ca_kernel(
        const float* __restrict__ w1, const float* __restrict__ b1,
        const float* __restrict__ w2, const float* __restrict__ b2) {
    __shared__ float t[BB*HID];
    const int tid = threadIdx.x;
    const int b = tid >> 6, c = tid & 63;
    if (c < HID) {
        float s = b1[c];
        for (int cc = 0; cc < CC; ++cc)
            s += w1[c*CC + cc] * (g_pool[b*CC + cc] * (1.f/(float)HWX));
        t[b*HID + c] = fmaxf(s, 0.f);
    }
    __syncthreads();
    float s = b2[c];
    #pragma unroll
    for (int h = 0; h < HID; ++h) s += w2[c*HID + h] * t[b*HID + h];
    g_cw[tid] = 1.f / (1.f + expf(-s));
}

// ---------------------------------------------------------------------------
// K4: Y GEMM: Y[p, tap] = sum_c (sa_w[c,tap]*cw[c]) * h[c,p]
// ---------------------------------------------------------------------------
__global__ __launch_bounds__(256) void y_gemm_kernel(
        const float* __restrict__ sa_w) {
    __shared__ uint32_t A_s[64*36];
    __shared__ uint32_t B_s[56*36];
    __shared__ float ts[64*33];

    const int tid = threadIdx.x;
    const int wid = tid >> 5, lid = tid & 31;
    const int b   = blockIdx.y;
    const int p0b = blockIdx.x * 64;

    for (int e = tid; e < 56*32; e += 256) {
        int tap = e >> 5, c2 = e & 31;
        __half2 v = __half2half2(__float2half(0.f));
        if (tap < 49) {
            float w0 = sa_w[(2*c2  )*49 + tap] * g_cw[b*CC + 2*c2];
            float w1 = sa_w[(2*c2+1)*49 + tap] * g_cw[b*CC + 2*c2 + 1];
            v = __floats2half2_rn(w0, w1);
        }
        B_s[tap*36 + c2] = *(const uint32_t*)&v;
    }

    const int px5 = tid & 31, cg = tid >> 5;
    #pragma unroll
    for (int sub = 0; sub < 2; ++sub) {
        __syncthreads();
        #pragma unroll
        for (int it = 0; it < 8; ++it) {
            int ch = it*8 + cg;
            ts[ch*33 + px5] = g_h[((size_t)(b*CC + ch))*HWX + p0b + sub*32 + px5];
        }
        __syncthreads();
        const int c2 = tid & 31;
        #pragma unroll
        for (int it = 0; it < 4; ++it) {
            int pl = it*8 + (tid >> 5);
            __half2 h = __floats2half2_rn(ts[(2*c2)*33 + pl], ts[(2*c2+1)*33 + pl]);
            A_s[(sub*32 + pl)*36 + c2] = *(const uint32_t*)&h;
        }
    }
    __syncthreads();

    const int mt = wid & 3, ng = wid >> 2;
    const int r4 = lid >> 2, klo = lid & 3;
    const int nt0 = ng*4, ntn = ng ? 3 : 4;

    float d0[4], d1[4], d2[4], d3[4];
    #pragma unroll
    for (int i = 0; i < 4; ++i) { d0[i]=0.f; d1[i]=0.f; d2[i]=0.f; d3[i]=0.f; }

    #pragma unroll
    for (int s = 0; s < 4; ++s) {
        const int kw = s*8 + klo;
        const int row = mt*16 + r4;
        uint32_t a0 = A_s[ row     *36 + kw    ];
        uint32_t a1 = A_s[(row + 8)*36 + kw    ];
        uint32_t a2 = A_s[ row     *36 + kw + 4];
        uint32_t a3 = A_s[(row + 8)*36 + kw + 4];
        #pragma unroll
        for (int ni = 0; ni < 4; ++ni) {
            if (ni < ntn) {
                const int orow = (nt0 + ni)*8 + r4;
                uint32_t b0 = B_s[orow*36 + kw];
                uint32_t b1 = B_s[orow*36 + kw + 4];
                MMA_F16(d0[ni], d1[ni], d2[ni], d3[ni], a0, a1, a2, a3, b0, b1);
            }
        }
    }

    const int pA = p0b + mt*16 + r4;
    const int pB = pA + 8;
    #pragma unroll
    for (int ni = 0; ni < 4; ++ni) {
        if (ni < ntn) {
            int t0 = (nt0 + ni)*8 + klo*2;
            int t1 = t0 + 1;
            if (t0 < 49) {
                g_Yh[((size_t)(b*49 + t0))*HWX + pA] = __float2half(d0[ni]);
                g_Yh[((size_t)(b*49 + t0))*HWX + pB] = __float2half(d2[ni]);
            }
            if (t1 < 49) {
                g_Yh[((size_t)(b*49 + t1))*HWX + pA] = __float2half(d1[ni]);
                g_Yh[((size_t)(b*49 + t1))*HWX + pB] = __float2half(d3[ni]);
            }
        }
    }
}

// ---------------------------------------------------------------------------
// K5: final: sw = sigmoid(sum_tap Y[p+Delta,tap] + b); out = h*cw*sw
// ---------------------------------------------------------------------------
__global__ __launch_bounds__(256) void final_kernel(
        const float* __restrict__ sa_b, float* __restrict__ out) {
    __shared__ float cws[CC];
    const int idx = blockIdx.x*256 + threadIdx.x;
    const int b = idx / HWX;
    const int p = idx % HWX;
    const int y = p / WW, x = p % WW;

    if (threadIdx.x < CC) cws[threadIdx.x] = g_cw[b*CC + threadIdx.x];
    __syncthreads();

    float acc = sa_b[0];
    const __half* Yb = g_Yh + (size_t)b*49*HWX;
    #pragma unroll
    for (int dy = 0; dy < 7; ++dy) {
        int yy = y + dy - 3;
        if ((unsigned)yy >= (unsigned)HH) continue;
        #pragma unroll
        for (int dx = 0; dx < 7; ++dx) {
            int xx = x + dx - 3;
            if ((unsigned)xx >= (unsigned)WW) continue;
            acc += __half2float(Yb[(size_t)(dy*7 + dx)*HWX + yy*WW + xx]);
        }
    }
    float sw = 1.f / (1.f + expf(-acc));

    const float* hb = g_h + (size_t)b*CC*HWX + p;
    float* ob = out + (size_t)b*CC*HWX + p;
    #pragma unroll 8
    for (int c = 0; c < CC; ++c)
        ob[(size_t)c*HWX] = hb[(size_t)c*HWX] * cws[c] * sw;
}

// ---------------------------------------------------------------------------
extern "C" void kernel_launch(void* const* d_in, const int* in_sizes, int n_in,
                              void* d_out, int out_size) {
    const float* x      = (const float*)d_in[0];
    const float* off_w  = (const float*)d_in[1];
    const float* off_b  = (const float*)d_in[2];
    const float* dw     = (const float*)d_in[3];
    const float* db     = (const float*)d_in[4];
    const float* bn_g   = (const float*)d_in[5];
    const float* bn_b   = (const float*)d_in[6];
    const float* bn_m   = (const float*)d_in[7];
    const float* bn_v   = (const float*)d_in[8];
    const float* ca_w1  = (const float*)d_in[9];
    const float* ca_b1  = (const float*)d_in[10];
    const float* ca_w2  = (const float*)d_in[11];
    const float* ca_b2  = (const float*)d_in[12];
    const float* sa_w   = (const float*)d_in[13];
    const float* sa_b   = (const float*)d_in[14];
    float* out = (float*)d_out;

    cudaFuncSetAttribute(offset_conv_kernel,
                         cudaFuncAttributeMaxDynamicSharedMemorySize,
                         OC_SMEM_BYTES);

    transpose_w_kernel<<<(9*CC*CC + 9*24*36 + 255)/256, 256>>>(dw, off_w);
    nhwc_kernel       <<<BB*HWX/32, 256>>>(x);
    offset_conv_kernel<<<dim3(WW/64, HH/4, BB), 256, OC_SMEM_BYTES>>>(off_b);
    deform_bn_kernel  <<<dim3(WW/64, HH, BB), 256>>>(db, bn_g, bn_b, bn_m, bn_v);
    ca_kernel         <<<1, 256>>>(ca_w1, ca_b1, ca_w2, ca_b2);
    y_gemm_kernel     <<<dim3(HWX/64, BB), 256>>>(sa_w);
    final_kernel      <<<BB*HWX/256, 256>>>(sa_b, out);
}